// round 10
// baseline (speedup 1.0000x reference)
#include <cuda_runtime.h>
#define NB 16384
#define NJ 15
#define NDEPTH 6
#define EPC 4
#define NTHR 512
#define RO(r) ((r)*128 + (((r)>>3)<<3))
#define RNOFF 2064
#define AOOFF 4128
#define QSOFF 6112
#define ESTRIDE 8992
#define WBUF_OFF (EPC*ESTRIDE)
#define CBUF_OFF (WBUF_OFF+6912)
#define LN2C_OFF (CBUF_OFF+144)
#define BFOLD_OFF (LN2C_OFF+128)
#define SMEM_FLOATS (BFOLD_OFF+384)
#define SMEM_BYTES (SMEM_FLOATS*4)

typedef unsigned long long u64t;
__device__ __forceinline__ u64t pk2(float lo, float hi) {
    u64t r; asm("mov.b64 %0, {%1,%2};" : "=l"(r) : "f"(lo), "f"(hi)); return r;
}
__device__ __forceinline__ void up2(u64t p, float& lo, float& hi) {
    asm("mov.b64 {%0,%1}, %2;" : "=f"(lo), "=f"(hi) : "l"(p));
}
__device__ __forceinline__ u64t fm2(u64t a, u64t b, u64t c) {
    u64t d; asm("fma.rn.f32x2 %0, %1, %2, %3;" : "=l"(d) : "l"(a), "l"(b), "l"(c)); return d;
}
__device__ __forceinline__ u64t ml2(u64t a, u64t b) {
    u64t d; asm("mul.rn.f32x2 %0, %1, %2;" : "=l"(d) : "l"(a), "l"(b)); return d;
}
__device__ __forceinline__ void row_stats4(float v0, float v1, float v2, float v3,
                                           float& mu, float& inv) {
    float s = v0+v1+v2+v3, ss = v0*v0+v1*v1+v2*v2+v3*v3;
    #pragma unroll
    for (int off = 16; off > 0; off >>= 1) {
        s  += __shfl_xor_sync(0xffffffffu, s,  off);
        ss += __shfl_xor_sync(0xffffffffu, ss, off);
    }
    mu = s * (1.0f/128.0f);
    inv = rsqrtf(ss * (1.0f/128.0f) - mu*mu + 1e-5f);
}

__global__ __launch_bounds__(NTHR, 1)
void jr_kernel(const float* __restrict__ joint, const float* __restrict__ rel,
               const float* __restrict__ Jqkv_w, const float* __restrict__ Jqkv_b,
               const float* __restrict__ Iqk_w,  const float* __restrict__ Iqk_b,
               const float* __restrict__ Iconv_w,const float* __restrict__ Iconv_b,
               const float* __restrict__ proj_w, const float* __restrict__ proj_b,
               const float* __restrict__ ln1_w,  const float* __restrict__ ln1_b,
               const float* __restrict__ ln2_w,  const float* __restrict__ ln2_b,
               const float* __restrict__ ln3_w,  const float* __restrict__ ln3_b,
               const float* __restrict__ fc1_w,  const float* __restrict__ fc1_b,
               const float* __restrict__ fc2_w,  const float* __restrict__ fc2_b,
               float* __restrict__ out)
{
    extern __shared__ float sm[];
    const int tid = threadIdx.x, wid = tid>>5, elem = wid>>2, ws = wid&3;
    const int lane = tid&31, c0 = lane*4, r0 = ws*4;
    const int rg = lane>>4, cg = lane&15, sd = cg>>3, dd = cg&7;

    // attention staging map: thread loads k=lane for 12 cols (colall = wid+16i)
    unsigned pkarr[12];
    #pragma unroll
    for (int i = 0; i < 12; i++) {
        int colall = wid + 16*i;
        int slot = colall/48;
        int c48 = colall - slot*48;
        int sIi = c48 >= 24;
        int c2 = c48 - sIi*24;
        int gcb = (c2>>3)*128 + slot*8 + (c2&7);
        pkarr[i] = (unsigned)(slot*1728 + c48*36 + lane)
                 | ((unsigned)gcb << 13) | ((unsigned)sIi << 31);
    }

    float* jn  = sm + elem*ESTRIDE;
    float* rn  = jn + RNOFF;
    float* ao  = jn + AOOFF;
    float* qsw = jn + QSOFF + ws*720;
    float* wbuf  = sm + WBUF_OFF;
    float* cbuf  = sm + CBUF_OFF;
    float* ln2c  = sm + LN2C_OFF;
    float* bfold = sm + BFOLD_OFF;

    const int eb = blockIdx.x*EPC + elem;
    const int e  = eb < NB ? eb : (NB-1);
    const long base = (long)e * (NJ*128);
    float st[12];

    float x[4][4];
    #pragma unroll
    for (int i = 0; i < 4; i++) {
        int row = r0+i, grow = row < NJ ? row : (NJ-1);
        float4 v = *reinterpret_cast<const float4*>(joint + base + grow*128 + c0);
        x[i][0]=v.x; x[i][1]=v.y; x[i][2]=v.z; x[i][3]=v.w;
    }
    #pragma unroll
    for (int i = 0; i < 4; i++) {
        int row = r0+i, grow = row < NJ ? row : (NJ-1);
        float4 v = *reinterpret_cast<const float4*>(rel + base + grow*128 + c0);
        float mu, inv;
        row_stats4(v.x, v.y, v.z, v.w, mu, inv);
        if (row < NJ) {
            float4 o;
            o.x=(v.x-mu)*inv; o.y=(v.y-mu)*inv; o.z=(v.z-mu)*inv; o.w=(v.w-mu)*inv;
            *reinterpret_cast<float4*>(rn + RO(row) + c0) = o;
        }
    }
    if (ws == 3) {
        float4 z = make_float4(0.f,0.f,0.f,0.f);
        *reinterpret_cast<float4*>(jn + RO(15) + c0) = z;
        *reinterpret_cast<float4*>(rn + RO(15) + c0) = z;
    }

    #pragma unroll 1
    for (int L = 0; L < NDEPTH; L++) {
        const float* Jw = Jqkv_w + L*49152;
        const float* Jb = Jqkv_b + L*384;
        const float* Iw = Iqk_w  + L*49152;
        const float* Pw = proj_w + L*16384;

        __syncthreads();
        if (tid < 128) {
            int d2 = tid>>4, m = tid&15;
            cbuf[tid] = (m < NJ) ? Iconv_w[L*(8*NJ) + d2*NJ + m] : 0.f;
            ln2c[tid] = ln2_w[L*128 + tid];
        } else if (tid < 144) {
            int m = tid-128;
            cbuf[128+m] = (m < NJ) ? Iconv_b[L*NJ + m] : 0.f;
        }
        if (tid < 384) {
            float a = Iqk_b[L*384 + tid];
            const float* wc = Iw + tid;
            const float* b2 = ln2_b + L*128;
            #pragma unroll 4
            for (int k = 0; k < 128; k++)
                a = fmaf(__ldg(b2+k), __ldg(wc + k*384), a);
            bfold[tid] = a;
        }
        {
            float4 w1 = *reinterpret_cast<const float4*>(ln1_w + L*128 + c0);
            float4 b1 = *reinterpret_cast<const float4*>(ln1_b + L*128 + c0);
            #pragma unroll
            for (int i = 0; i < 4; i++) {
                float mu, inv;
                row_stats4(x[i][0], x[i][1], x[i][2], x[i][3], mu, inv);
                int row = r0+i;
                if (row < NJ) {
                    float4 o;
                    o.x = fmaf((x[i][0]-mu)*inv, w1.x, b1.x);
                    o.y = fmaf((x[i][1]-mu)*inv, w1.y, b1.y);
                    o.z = fmaf((x[i][2]-mu)*inv, w1.z, b1.z);
                    o.w = fmaf((x[i][3]-mu)*inv, w1.w, b1.w);
                    *reinterpret_cast<float4*>(jn + RO(row) + c0) = o;
                }
            }
        }
        __syncthreads();

        // prefetch attention chunk (r=0,q=0)
        {
            const float* bJ = Jw + lane*384;
            const float* bI = Iw + lane*384;
            float l2 = ln2c[lane];
            #pragma unroll
            for (int i = 0; i < 12; i++) {
                unsigned pkv = pkarr[i];
                int gcb = (pkv>>13) & 511;
                st[i] = (pkv>>31) ? bI[gcb]*l2 : bJ[gcb];
            }
        }
        #pragma unroll 1
        for (int r = 0; r < 4; r++) {
            const int h = r*4 + ws;
            u64t acc[3][8];
            #pragma unroll
            for (int mt = 0; mt < 3; mt++) {
                float bv = sd ? bfold[mt*128 + h*8 + dd] : __ldg(Jb + mt*128 + h*8 + dd);
                #pragma unroll
                for (int i = 0; i < 8; i++) acc[mt][i] = pk2(bv, 0.f);
            }
            #pragma unroll 1
            for (int q = 0; q < 4; q++) {
                __syncthreads();
                #pragma unroll
                for (int i = 0; i < 12; i++) wbuf[pkarr[i] & 8191] = st[i];
                __syncthreads();
                {
                    int nr = r, nq = q + 1;
                    if (nq == 4) { nq = 0; nr++; }
                    if (nr < 4) {
                        const float* bJ = Jw + (nq*32+lane)*384 + nr*32;
                        const float* bI = Iw + (nq*32+lane)*384 + nr*32;
                        float l2 = ln2c[nq*32+lane];
                        #pragma unroll
                        for (int i = 0; i < 12; i++) {
                            unsigned pkv = pkarr[i];
                            int gcb = (pkv>>13) & 511;
                            st[i] = (pkv>>31) ? bI[gcb]*l2 : bJ[gcb];
                        }
                    }
                }
                const float* ap  = jn + sd*RNOFF + rg*1032 + q*32;
                const float* w0p = wbuf + ws*1728 + (sd*24 + dd)*36;
                const float* w1p = w0p + 288;
                const float* w2p = w0p + 576;
                #pragma unroll 4
                for (int k = 0; k < 32; k += 4) {
                    ulonglong2 W0 = *reinterpret_cast<const ulonglong2*>(w0p + k);
                    ulonglong2 W1 = *reinterpret_cast<const ulonglong2*>(w1p + k);
                    ulonglong2 W2 = *reinterpret_cast<const ulonglong2*>(w2p + k);
                    #pragma unroll
                    for (int i = 0; i < 8; i++) {
                        ulonglong2 A = *reinterpret_cast<const ulonglong2*>(ap + i*128 + k);
                        acc[0][i] = fm2(A.x, W0.x, acc[0][i]);
                        acc[0][i] = fm2(A.y, W0.y, acc[0][i]);
                        acc[1][i] = fm2(A.x, W1.x, acc[1][i]);
                        acc[1][i] = fm2(A.y, W1.y, acc[1][i]);
                        acc[2][i] = fm2(A.x, W2.x, acc[2][i]);
                        acc[2][i] = fm2(A.y, W2.y, acc[2][i]);
                    }
                }
            }
            #pragma unroll
            for (int mt = 0; mt < 3; mt++) {
                #pragma unroll
                for (int i = 0; i < 8; i++) {
                    int row = rg*8 + i;
                    if (row < NJ) {
                        float lo, hi; up2(acc[mt][i], lo, hi);
                        qsw[(sd*3+mt)*120 + row*8 + dd] = lo + hi;
                    }
                }
            }
            __syncwarp();
            if (lane < NJ) {
                const int n = lane;
                ulonglong2 Q0 = *reinterpret_cast<const ulonglong2*>(qsw + 0*120 + n*8);
                ulonglong2 Q1 = *reinterpret_cast<const ulonglong2*>(qsw + 0*120 + n*8 + 4);
                ulonglong2 U0 = *reinterpret_cast<const ulonglong2*>(qsw + 3*120 + n*8);
                ulonglong2 U1 = *reinterpret_cast<const ulonglong2*>(qsw + 3*120 + n*8 + 4);
                float iv[8];
                {
                    float4 v0 = *reinterpret_cast<float4*>(qsw + 5*120 + n*8);
                    float4 v1 = *reinterpret_cast<float4*>(qsw + 5*120 + n*8 + 4);
                    iv[0]=v0.x; iv[1]=v0.y; iv[2]=v0.z; iv[3]=v0.w;
                    iv[4]=v1.x; iv[5]=v1.y; iv[6]=v1.z; iv[7]=v1.w;
                }
                float sc[NJ];
                #pragma unroll
                for (int m = 0; m < NJ; m++) {
                    ulonglong2 K0 = *reinterpret_cast<const ulonglong2*>(qsw + 1*120 + m*8);
                    ulonglong2 K1 = *reinterpret_cast<const ulonglong2*>(qsw + 1*120 + m*8 + 4);
                    ulonglong2 I0 = *reinterpret_cast<const ulonglong2*>(qsw + 4*120 + m*8);
                    ulonglong2 I1 = *reinterpret_cast<const ulonglong2*>(qsw + 4*120 + m*8 + 4);
                    u64t t2 = ml2(Q0.x, K0.x);
                    t2 = fm2(Q0.y, K0.y, t2);
                    t2 = fm2(Q1.x, K1.x, t2);
                    t2 = fm2(Q1.y, K1.y, t2);
                    t2 = fm2(U0.x, I0.x, t2);
                    t2 = fm2(U0.y, I0.y, t2);
                    t2 = fm2(U1.x, I1.x, t2);
                    t2 = fm2(U1.y, I1.y, t2);
                    float lo, hi; up2(t2, lo, hi);
                    float t = cbuf[128+m];
                    #pragma unroll
                    for (int d3 = 0; d3 < 8; d3++)
                        t = fmaf(iv[d3], cbuf[d3*16 + m], t);
                    sc[m] = (t + lo + hi) * 0.6f;
                }
                float mx = sc[0];
                #pragma unroll
                for (int m = 1; m < NJ; m++) mx = fmaxf(mx, sc[m]);
                float sum = 0.f;
                #pragma unroll
                for (int m = 0; m < NJ; m++) { sc[m] = __expf(sc[m]-mx); sum += sc[m]; }
                float rs = 1.0f/sum;
                u64t o0=0ull, o1=0ull, o2=0ull, o3=0ull;
                #pragma unroll
                for (int m = 0; m < NJ; m++) {
                    float pm = sc[m]*rs;
                    u64t pm2 = pk2(pm, pm);
                    ulonglong2 J0 = *reinterpret_cast<const ulonglong2*>(qsw + 2*120 + m*8);
                    ulonglong2 J1 = *reinterpret_cast<const ulonglong2*>(qsw + 2*120 + m*8 + 4);
                    o0 = fm2(pm2, J0.x, o0);
                    o1 = fm2(pm2, J0.y, o1);
                    o2 = fm2(pm2, J1.x, o2);
                    o3 = fm2(pm2, J1.y, o3);
                }
                *reinterpret_cast<ulonglong2*>(ao + n*132 + h*8)     = make_ulonglong2(o0, o1);
                *reinterpret_cast<ulonglong2*>(ao + n*132 + h*8 + 4) = make_ulonglong2(o2, o3);
            }
        }

        // proj: 8 elems/thread staging, exact
        float sp[8];
        #pragma unroll
        for (int i = 0; i < 8; i++) sp[i] = Pw[tid + i*NTHR];
        #pragma unroll 1
        for (int kc = 0; kc < 4; kc++) {
            __syncthreads();
            #pragma unroll
            for (int i = 0; i < 8; i++) wbuf[tid + i*NTHR] = sp[i];
            __syncthreads();
            if (kc < 3) {
                #pragma unroll
                for (int i = 0; i < 8; i++) sp[i] = Pw[(kc+1)*4096 + tid + i*NTHR];
            }
            u64t xa[4], xb[4];
            #pragma unroll
            for (int i = 0; i < 4; i++) { xa[i]=pk2(x[i][0],x[i][1]); xb[i]=pk2(x[i][2],x[i][3]); }
            #pragma unroll 1
            for (int kk4 = 0; kk4 < 8; kk4++) {
                float a4[4][4];
                #pragma unroll
                for (int i = 0; i < 4; i++) {
                    int row = r0+i; row = row < NJ ? row : (NJ-1);
                    float4 t = *reinterpret_cast<float4*>(ao + row*132 + kc*32 + kk4*4);
                    a4[i][0]=t.x; a4[i][1]=t.y; a4[i][2]=t.z; a4[i][3]=t.w;
                }
                #pragma unroll
                for (int j = 0; j < 4; j++) {
                    ulonglong2 Wv = *reinterpret_cast<const ulonglong2*>(wbuf + (kk4*4+j)*128 + c0);
                    #pragma unroll
                    for (int i = 0; i < 4; i++) {
                        u64t ad = pk2(a4[i][j], a4[i][j]);
                        xa[i] = fm2(ad, Wv.x, xa[i]);
                        xb[i] = fm2(ad, Wv.y, xb[i]);
                    }
                }
            }
            #pragma unroll
            for (int i = 0; i < 4; i++) { up2(xa[i],x[i][0],x[i][1]); up2(xb[i],x[i][2],x[i][3]); }
        }
        {
            float4 pb = *reinterpret_cast<const float4*>(proj_b + L*128 + c0);
            #pragma unroll
            for (int i = 0; i < 4; i++) {
                x[i][0]+=pb.x; x[i][1]+=pb.y; x[i][2]+=pb.z; x[i][3]+=pb.w;
            }
        }
        {
            float4 w3 = *reinterpret_cast<const float4*>(ln3_w + L*128 + c0);
            float4 b3 = *reinterpret_cast<const float4*>(ln3_b + L*128 + c0);
            #pragma unroll
            for (int i = 0; i < 4; i++) {
                float mu, inv;
                row_stats4(x[i][0], x[i][1], x[i][2], x[i][3], mu, inv);
                int row = r0+i;
                if (row < NJ) {
                    float4 o;
                    o.x = fmaf((x[i][0]-mu)*inv, w3.x, b3.x);
                    o.y = fmaf((x[i][1]-mu)*inv, w3.y, b3.y);
                    o.z = fmaf((x[i][2]-mu)*inv, w3.z, b3.z);
                    o.w = fmaf((x[i][3]-mu)*inv, w3.w, b3.w);
                    *reinterpret_cast<float4*>(jn + RO(row) + c0) = o;
                }
            }
        }
        u64t ha2[4];
        {
            float2 fb = *reinterpret_cast<const float2*>(fc1_b + L*64 + lane*2);
            #pragma unroll
            for (int i = 0; i < 4; i++) ha2[i] = pk2(fb.x, fb.y);
        }
        #pragma unroll
        for (int i = 0; i < 8; i++) sp[i] = fc1_w[L*8192 + tid + i*NTHR];
        #pragma unroll 1
        for (int kc = 0; kc < 2; kc++) {
            __syncthreads();
            #pragma unroll
            for (int i = 0; i < 8; i++) wbuf[tid + i*NTHR] = sp[i];
            __syncthreads();
            if (kc < 1) {
                #pragma unroll
                for (int i = 0; i < 8; i++) sp[i] = fc1_w[L*8192 + 4096 + tid + i*NTHR];
            }
            #pragma unroll 1
            for (int kk4 = 0; kk4 < 16; kk4++) {
                float a4[4][4];
                #pragma unroll
                for (int i = 0; i < 4; i++) {
                    int row = r0+i; row = row < NJ ? row : (NJ-1);
                    float4 t = *reinterpret_cast<float4*>(jn + RO(row) + kc*64 + kk4*4);
                    a4[i][0]=t.x; a4[i][1]=t.y; a4[i][2]=t.z; a4[i][3]=t.w;
                }
                #pragma unroll
                for (int j = 0; j < 4; j++) {
                    u64t wv = *reinterpret_cast<const u64t*>(wbuf + (kk4*4+j)*64 + lane*2);
                    #pragma unroll
                    for (int i = 0; i < 4; i++) {
                        u64t ad = pk2(a4[i][j], a4[i][j]);
                        ha2[i] = fm2(ad, wv, ha2[i]);
                    }
                }
            }
        }
        #pragma unroll
        for (int i = 0; i < 4; i++) {
            int row = r0+i;
            if (row < NJ) {
                float h0, h1; up2(ha2[i], h0, h1);
                float g0 = 0.5f*h0*(1.0f + erff(h0*0.70710678118654752f));
                float g1 = 0.5f*h1*(1.0f + erff(h1*0.70710678118654752f));
                *reinterpret_cast<float2*>(ao + row*64 + lane*2) = make_float2(g0, g1);
            }
        }
        __syncwarp();
        #pragma unroll
        for (int i = 0; i < 8; i++) sp[i] = fc2_w[L*8192 + tid + i*NTHR];
        #pragma unroll 1
        for (int kc = 0; kc < 2; kc++) {
            __syncthreads();
            #pragma unroll
            for (int i = 0; i < 8; i++) wbuf[tid + i*NTHR] = sp[i];
            __syncthreads();
            if (kc < 1) {
                #pragma unroll
                for (int i = 0; i < 8; i++) sp[i] = fc2_w[L*8192 + 4096 + tid + i*NTHR];
            }
            u64t xa[4], xb[4];
            #pragma unroll
            for (int i = 0; i < 4; i++) { xa[i]=pk2(x[i][0],x[i][1]); xb[i]=pk2(x[i][2],x[i][3]); }
            #pragma unroll 1
            for (int kk4 = 0; kk4 < 8; kk4++) {
                float a4[4][4];
                #pragma unroll
                for (int i = 0; i < 4; i++) {
                    int row = r0+i; row = row < NJ ? row : (NJ-1);
                    float4 t = *reinterpret_cast<float4*>(ao + row*64 + kc*32 + kk4*4);
                    a4[i][0]=t.x; a4[i][1]=t.y; a4[i][2]=t.z; a4[i][3]=t.w;
                }
                #pragma unroll
                for (int j = 0; j < 4; j++) {
                    ulonglong2 Wv = *reinterpret_cast<const ulonglong2*>(wbuf + (kk4*4+j)*128 + c0);
                    #pragma unroll
                    for (int i = 0; i < 4; i++) {
                        u64t ad = pk2(a4[i][j], a4[i][j]);
                        xa[i] = fm2(ad, Wv.x, xa[i]);
                        xb[i] = fm2(ad, Wv.y, xb[i]);
                    }
                }
            }
            #pragma unroll
            for (int i = 0; i < 4; i++) { up2(xa[i],x[i][0],x[i][1]); up2(xb[i],x[i][2],x[i][3]); }
        }
        {
            float4 fb = *reinterpret_cast<const float4*>(fc2_b + L*128 + c0);
            #pragma unroll
            for (int i = 0; i < 4; i++) {
                x[i][0]+=fb.x; x[i][1]+=fb.y; x[i][2]+=fb.z; x[i][3]+=fb.w;
            }
        }
    }

    if (eb < NB) {
        #pragma unroll
        for (int i = 0; i < 4; i++) {
            int row = r0+i;
            if (row < NJ)
                *reinterpret_cast<float4*>(out + base + row*128 + c0) =
                    make_float4(x[i][0], x[i][1], x[i][2], x[i][3]);
        }
    }
}

extern "C" void kernel_launch(void* const* d_in, const int* in_sizes, int n_in,
                              void* d_out, int out_size) {
    (void)in_sizes; (void)n_in; (void)out_size;
    const float** p = (const float**)d_in;
    cudaFuncSetAttribute(jr_kernel, cudaFuncAttributeMaxDynamicSharedMemorySize,
                         SMEM_BYTES);
    jr_kernel<<<(NB + EPC - 1)/EPC, NTHR, SMEM_BYTES>>>(
        p[0], p[1], p[2], p[3], p[4], p[5], p[6], p[7], p[8], p[9],
        p[10], p[11], p[12], p[13], p[14], p[15], p[16], p[17], p[18], p[19],
        (float*)d_out);
}

// round 11
// speedup vs baseline: 1.6172x; 1.6172x over previous
#include <cuda_runtime.h>
#define NB 16384
#define NJ 15
#define NDEPTH 6
#define EPC 6
#define NTHR 384
#define RO(r) ((r)*128 + (((r)>>3)<<3))
#define RNOFF 2064
#define AOOFF 4128
#define QSOFF 6112
#define ESTRIDE 7552
#define WBUF_OFF (EPC*ESTRIDE)
#define CBUF_OFF (WBUF_OFF+6528)
#define LN2C_OFF (CBUF_OFF+144)
#define BFOLD_OFF (LN2C_OFF+128)
#define SMEM_FLOATS (BFOLD_OFF+384)
#define SMEM_BYTES (SMEM_FLOATS*4)

typedef unsigned long long u64t;
__device__ __forceinline__ u64t pk2(float lo, float hi) {
    u64t r; asm("mov.b64 %0, {%1,%2};" : "=l"(r) : "f"(lo), "f"(hi)); return r;
}
__device__ __forceinline__ void up2(u64t p, float& lo, float& hi) {
    asm("mov.b64 {%0,%1}, %2;" : "=f"(lo), "=f"(hi) : "l"(p));
}
__device__ __forceinline__ u64t fm2(u64t a, u64t b, u64t c) {
    u64t d; asm("fma.rn.f32x2 %0, %1, %2, %3;" : "=l"(d) : "l"(a), "l"(b), "l"(c)); return d;
}
__device__ __forceinline__ u64t ml2(u64t a, u64t b) {
    u64t d; asm("mul.rn.f32x2 %0, %1, %2;" : "=l"(d) : "l"(a), "l"(b)); return d;
}
__device__ __forceinline__ void row_stats4(float v0, float v1, float v2, float v3,
                                           float& mu, float& inv) {
    float s = v0+v1+v2+v3, ss = v0*v0+v1*v1+v2*v2+v3*v3;
    #pragma unroll
    for (int off = 16; off > 0; off >>= 1) {
        s  += __shfl_xor_sync(0xffffffffu, s,  off);
        ss += __shfl_xor_sync(0xffffffffu, ss, off);
    }
    mu = s * (1.0f/128.0f);
    inv = rsqrtf(ss * (1.0f/128.0f) - mu*mu + 1e-5f);
}

__global__ __launch_bounds__(NTHR, 1)
void jr_kernel(const float* __restrict__ joint, const float* __restrict__ rel,
               const float* __restrict__ Jqkv_w, const float* __restrict__ Jqkv_b,
               const float* __restrict__ Iqk_w,  const float* __restrict__ Iqk_b,
               const float* __restrict__ Iconv_w,const float* __restrict__ Iconv_b,
               const float* __restrict__ proj_w, const float* __restrict__ proj_b,
               const float* __restrict__ ln1_w,  const float* __restrict__ ln1_b,
               const float* __restrict__ ln2_w,  const float* __restrict__ ln2_b,
               const float* __restrict__ ln3_w,  const float* __restrict__ ln3_b,
               const float* __restrict__ fc1_w,  const float* __restrict__ fc1_b,
               const float* __restrict__ fc2_w,  const float* __restrict__ fc2_b,
               float* __restrict__ out)
{
    extern __shared__ float sm[];
    const int tid = threadIdx.x, wid = tid>>5, elem = wid>>1, ws = wid&1;
    const int lane = tid&31, c0 = lane*4, r0 = ws*8;
    const int rg = lane>>4, cg = lane&15, sd = cg>>3, dd = cg&7;
    const int kk0 = tid/96, c96 = tid - kk0*96;
    const int sslot = c96 >= 48;
    const int scol = c96 - sslot*48;
    const int sI = scol >= 24;
    const int sc2 = scol - sI*24;
    const int scc = (sc2>>3)*128 + (sc2&7) + sslot*8;
    const int ssm = sslot*3264 + scol*68 + kk0;

    float* jn  = sm + elem*ESTRIDE;
    float* rn  = jn + RNOFF;
    float* ao  = jn + AOOFF;
    float* qsw = jn + QSOFF + ws*720;
    float* wbuf  = sm + WBUF_OFF;
    float* cbuf  = sm + CBUF_OFF;
    float* ln2c  = sm + LN2C_OFF;
    float* bfold = sm + BFOLD_OFF;

    const int eb = blockIdx.x*EPC + elem;
    const int e  = eb < NB ? eb : (NB-1);
    const long base = (long)e * (NJ*128);
    float st[16];

    float x[8][4];
    #pragma unroll
    for (int i = 0; i < 8; i++) {
        int row = r0+i, grow = row < NJ ? row : (NJ-1);
        float4 v = *reinterpret_cast<const float4*>(joint + base + grow*128 + c0);
        x[i][0]=v.x; x[i][1]=v.y; x[i][2]=v.z; x[i][3]=v.w;
    }
    #pragma unroll
    for (int i = 0; i < 8; i++) {
        int row = r0+i, grow = row < NJ ? row : (NJ-1);
        float4 v = *reinterpret_cast<const float4*>(rel + base + grow*128 + c0);
        float mu, inv;
        row_stats4(v.x, v.y, v.z, v.w, mu, inv);
        if (row < NJ) {
            float4 o;
            o.x=(v.x-mu)*inv; o.y=(v.y-mu)*inv; o.z=(v.z-mu)*inv; o.w=(v.w-mu)*inv;
            *reinterpret_cast<float4*>(rn + RO(row) + c0) = o;
        }
    }
    {
        float4 z = make_float4(0.f,0.f,0.f,0.f);
        *reinterpret_cast<float4*>(jn + RO(15) + c0) = z;
        *reinterpret_cast<float4*>(rn + RO(15) + c0) = z;
    }

    #pragma unroll 1
    for (int L = 0; L < NDEPTH; L++) {
        const float* Jw = Jqkv_w + L*49152;
        const float* Jb = Jqkv_b + L*384;
        const float* Iw = Iqk_w  + L*49152;
        const float* Pw = proj_w + L*16384;
        const float* Sw = sI ? Iw : Jw;

        __syncthreads();
        if (tid < 128) {
            int d2 = tid>>4, m = tid&15;
            cbuf[tid] = (m < NJ) ? Iconv_w[L*(8*NJ) + d2*NJ + m] : 0.f;
            ln2c[tid] = ln2_w[L*128 + tid];
        } else if (tid < 144) {
            int m = tid-128;
            cbuf[128+m] = (m < NJ) ? Iconv_b[L*NJ + m] : 0.f;
        }
        if (tid < 384) {
            float a = Iqk_b[L*384 + tid];
            const float* wc = Iw + tid;
            const float* b2 = ln2_b + L*128;
            #pragma unroll 4
            for (int k = 0; k < 128; k++)
                a = fmaf(__ldg(b2+k), __ldg(wc + k*384), a);
            bfold[tid] = a;
        }
        {
            float4 w1 = *reinterpret_cast<const float4*>(ln1_w + L*128 + c0);
            float4 b1 = *reinterpret_cast<const float4*>(ln1_b + L*128 + c0);
            #pragma unroll
            for (int i = 0; i < 8; i++) {
                float mu, inv;
                row_stats4(x[i][0], x[i][1], x[i][2], x[i][3], mu, inv);
                int row = r0+i;
                if (row < NJ) {
                    float4 o;
                    o.x = fmaf((x[i][0]-mu)*inv, w1.x, b1.x);
                    o.y = fmaf((x[i][1]-mu)*inv, w1.y, b1.y);
                    o.z = fmaf((x[i][2]-mu)*inv, w1.z, b1.z);
                    o.w = fmaf((x[i][3]-mu)*inv, w1.w, b1.w);
                    *reinterpret_cast<float4*>(jn + RO(row) + c0) = o;
                }
            }
        }
        __syncthreads();

        {
            const float* gp = Sw + scc + kk0*384;
            const float* lp = ln2c + kk0;
            #pragma unroll
            for (int i = 0; i < 16; i++)
                st[i] = sI ? gp[i*1536]*lp[4*i] : gp[i*1536];
        }
        #pragma unroll 1
        for (int r = 0; r < 8; r++) {
            const int h = r*2 + ws;
            u64t acc[3][8];
            #pragma unroll
            for (int mt = 0; mt < 3; mt++) {
                float bv = sd ? bfold[mt*128 + h*8 + dd] : __ldg(Jb + mt*128 + h*8 + dd);
                #pragma unroll
                for (int i = 0; i < 8; i++) acc[mt][i] = pk2(bv, 0.f);
            }
            #pragma unroll 1
            for (int q = 0; q < 2; q++) {
                __syncthreads();
                #pragma unroll
                for (int i = 0; i < 16; i++) wbuf[ssm + 4*i] = st[i];
                __syncthreads();
                {
                    int nr = r, nq = q + 1;
                    if (nq == 2) { nq = 0; nr++; }
                    if (nr < 8) {
                        const float* gp = Sw + scc + nr*16 + nq*24576 + kk0*384;
                        const float* lp = ln2c + nq*64 + kk0;
                        #pragma unroll
                        for (int i = 0; i < 16; i++)
                            st[i] = sI ? gp[i*1536]*lp[4*i] : gp[i*1536];
                    }
                }
                const float* ap  = jn + sd*RNOFF + rg*1032 + q*64;
                const float* w0p = wbuf + ws*3264 + (sd*24 + dd)*68;
                const float* w1p = w0p + 544;
                const float* w2p = w0p + 1088;
                #pragma unroll 4
                for (int k = 0; k < 64; k += 4) {
                    ulonglong2 W0 = *reinterpret_cast<const ulonglong2*>(w0p + k);
                    ulonglong2 W1 = *reinterpret_cast<const ulonglong2*>(w1p + k);
                    ulonglong2 W2 = *reinterpret_cast<const ulonglong2*>(w2p + k);
                    #pragma unroll
                    for (int i = 0; i < 8; i++) {
                        ulonglong2 A = *reinterpret_cast<const ulonglong2*>(ap + i*128 + k);
                        acc[0][i] = fm2(A.x, W0.x, acc[0][i]);
                        acc[0][i] = fm2(A.y, W0.y, acc[0][i]);
                        acc[1][i] = fm2(A.x, W1.x, acc[1][i]);
                        acc[1][i] = fm2(A.y, W1.y, acc[1][i]);
                        acc[2][i] = fm2(A.x, W2.x, acc[2][i]);
                        acc[2][i] = fm2(A.y, W2.y, acc[2][i]);
                    }
                }
            }
            #pragma unroll
            for (int mt = 0; mt < 3; mt++) {
                #pragma unroll
                for (int i = 0; i < 8; i++) {
                    int row = rg*8 + i;
                    if (row < NJ) {
                        float lo, hi; up2(acc[mt][i], lo, hi);
                        qsw[(sd*3+mt)*120 + row*8 + dd] = lo + hi;
                    }
                }
            }
            __syncwarp();
            // pair-split scores/softmax/AV: lane (pr, n), 30 active lanes
            {
                const int pr = lane >> 4;
                const int n  = lane & 15;
                if (n < NJ) {
                    float sc[NJ];
                    if (pr == 0) {
                        ulonglong2 Q0 = *reinterpret_cast<const ulonglong2*>(qsw + 0*120 + n*8);
                        ulonglong2 Q1 = *reinterpret_cast<const ulonglong2*>(qsw + 0*120 + n*8 + 4);
                        #pragma unroll
                        for (int m = 0; m < NJ; m++) {
                            ulonglong2 K0 = *reinterpret_cast<const ulonglong2*>(qsw + 1*120 + m*8);
                            ulonglong2 K1 = *reinterpret_cast<const ulonglong2*>(qsw + 1*120 + m*8 + 4);
                            u64t t2 = ml2(Q0.x, K0.x);
                            t2 = fm2(Q0.y, K0.y, t2);
                            t2 = fm2(Q1.x, K1.x, t2);
                            t2 = fm2(Q1.y, K1.y, t2);
                            float lo, hi; up2(t2, lo, hi);
                            sc[m] = lo + hi;
                        }
                    } else {
                        ulonglong2 U0 = *reinterpret_cast<const ulonglong2*>(qsw + 3*120 + n*8);
                        ulonglong2 U1 = *reinterpret_cast<const ulonglong2*>(qsw + 3*120 + n*8 + 4);
                        float iv[8];
                        {
                            float4 v0 = *reinterpret_cast<float4*>(qsw + 5*120 + n*8);
                            float4 v1 = *reinterpret_cast<float4*>(qsw + 5*120 + n*8 + 4);
                            iv[0]=v0.x; iv[1]=v0.y; iv[2]=v0.z; iv[3]=v0.w;
                            iv[4]=v1.x; iv[5]=v1.y; iv[6]=v1.z; iv[7]=v1.w;
                        }
                        #pragma unroll
                        for (int m = 0; m < NJ; m++) {
                            ulonglong2 I0 = *reinterpret_cast<const ulonglong2*>(qsw + 4*120 + m*8);
                            ulonglong2 I1 = *reinterpret_cast<const ulonglong2*>(qsw + 4*120 + m*8 + 4);
                            u64t t2 = ml2(U0.x, I0.x);
                            t2 = fm2(U0.y, I0.y, t2);
                            t2 = fm2(U1.x, I1.x, t2);
                            t2 = fm2(U1.y, I1.y, t2);
                            float lo, hi; up2(t2, lo, hi);
                            float t = cbuf[128+m];
                            #pragma unroll
                            for (int d3 = 0; d3 < 8; d3++)
                                t = fmaf(iv[d3], cbuf[d3*16 + m], t);
                            sc[m] = t + lo + hi;
                        }
                    }
                    #pragma unroll
                    for (int m = 0; m < NJ; m++) {
                        float o2 = __shfl_xor_sync(0x7fff7fffu, sc[m], 16);
                        sc[m] = (sc[m] + o2) * 0.6f;
                    }
                    float mx = sc[0];
                    #pragma unroll
                    for (int m = 1; m < NJ; m++) mx = fmaxf(mx, sc[m]);
                    float sum = 0.f;
                    #pragma unroll
                    for (int m = 0; m < NJ; m++) { sc[m] = __expf(sc[m]-mx); sum += sc[m]; }
                    float rs = 1.0f/sum;
                    u64t o0 = 0ull, o1 = 0ull;
                    const float* jvh = qsw + 2*120 + pr*4;
                    #pragma unroll
                    for (int m = 0; m < NJ; m++) {
                        float pm = sc[m]*rs;
                        u64t pm2 = pk2(pm, pm);
                        ulonglong2 Jh = *reinterpret_cast<const ulonglong2*>(jvh + m*8);
                        o0 = fm2(pm2, Jh.x, o0);
                        o1 = fm2(pm2, Jh.y, o1);
                    }
                    *reinterpret_cast<ulonglong2*>(ao + n*132 + h*8 + pr*4) =
                        make_ulonglong2(o0, o1);
                }
            }
        }

        // proj
        #pragma unroll
        for (int i = 0; i < 11; i++) {
            int idx = tid + i*384;
            if (idx < 4096) st[i] = Pw[(idx>>7)*128 + (idx&127)];
        }
        #pragma unroll 1
        for (int kc = 0; kc < 4; kc++) {
            __syncthreads();
            #pragma unroll
            for (int i = 0; i < 11; i++) {
                int idx = tid + i*384;
                if (idx < 4096) wbuf[idx] = st[i];
            }
            __syncthreads();
            if (kc < 3) {
                #pragma unroll
                for (int i = 0; i < 11; i++) {
                    int idx = tid + i*384;
                    if (idx < 4096) st[i] = Pw[((kc+1)*32 + (idx>>7))*128 + (idx&127)];
                }
            }
            u64t xa[8], xb[8];
            #pragma unroll
            for (int i = 0; i < 8; i++) { xa[i]=pk2(x[i][0],x[i][1]); xb[i]=pk2(x[i][2],x[i][3]); }
            #pragma unroll 1
            for (int kk4 = 0; kk4 < 8; kk4++) {
                float a4[8][4];
                #pragma unroll
                for (int i = 0; i < 8; i++) {
                    int row = r0+i; row = row < NJ ? row : (NJ-1);
                    float4 t = *reinterpret_cast<float4*>(ao + row*132 + kc*32 + kk4*4);
                    a4[i][0]=t.x; a4[i][1]=t.y; a4[i][2]=t.z; a4[i][3]=t.w;
                }
                #pragma unroll
                for (int j = 0; j < 4; j++) {
                    ulonglong2 Wv = *reinterpret_cast<const ulonglong2*>(wbuf + (kk4*4+j)*128 + c0);
                    #pragma unroll
                    for (int i = 0; i < 8; i++) {
                        u64t ad = pk2(a4[i][j], a4[i][j]);
                        xa[i] = fm2(ad, Wv.x, xa[i]);
                        xb[i] = fm2(ad, Wv.y, xb[i]);
                    }
                }
            }
            #pragma unroll
            for (int i = 0; i < 8; i++) { up2(xa[i],x[i][0],x[i][1]); up2(xb[i],x[i][2],x[i][3]); }
        }
        {
            float4 pb = *reinterpret_cast<const float4*>(proj_b + L*128 + c0);
            #pragma unroll
            for (int i = 0; i < 8; i++) {
                x[i][0]+=pb.x; x[i][1]+=pb.y; x[i][2]+=pb.z; x[i][3]+=pb.w;
            }
        }
        {
            float4 w3 = *reinterpret_cast<const float4*>(ln3_w + L*128 + c0);
            float4 b3 = *reinterpret_cast<const float4*>(ln3_b + L*128 + c0);
            #pragma unroll
            for (int i = 0; i < 8; i++) {
                float mu, inv;
                row_stats4(x[i][0], x[i][1], x[i][2], x[i][3], mu, inv);
                int row = r0+i;
                if (row < NJ) {
                    float4 o;
                    o.x = fmaf((x[i][0]-mu)*inv, w3.x, b3.x);
                    o.y = fmaf((x[i][1]-mu)*inv, w3.y, b3.y);
                    o.z = fmaf((x[i][2]-mu)*inv, w3.z, b3.z);
                    o.w = fmaf((x[i][3]-mu)*inv, w3.w, b3.w);
                    *reinterpret_cast<float4*>(jn + RO(row) + c0) = o;
                }
            }
        }
        u64t ha2[8];
        {
            float2 fb = *reinterpret_cast<const float2*>(fc1_b + L*64 + lane*2);
            #pragma unroll
            for (int i = 0; i < 8; i++) ha2[i] = pk2(fb.x, fb.y);
        }
        #pragma unroll
        for (int i = 0; i < 11; i++) {
            int idx = tid + i*384;
            if (idx < 4096) st[i] = fc1_w[L*8192 + idx];
        }
        #pragma unroll 1
        for (int kc = 0; kc < 2; kc++) {
            __syncthreads();
            #pragma unroll
            for (int i = 0; i < 11; i++) {
                int idx = tid + i*384;
                if (idx < 4096) wbuf[idx] = st[i];
            }
            __syncthreads();
            if (kc < 1) {
                #pragma unroll
                for (int i = 0; i < 11; i++) {
                    int idx = tid + i*384;
                    if (idx < 4096) st[i] = fc1_w[L*8192 + 4096 + idx];
                }
            }
            #pragma unroll 1
            for (int kk4 = 0; kk4 < 16; kk4++) {
                float a4[8][4];
                #pragma unroll
                for (int i = 0; i < 8; i++) {
                    int row = r0+i; row = row < NJ ? row : (NJ-1);
                    float4 t = *reinterpret_cast<float4*>(jn + RO(row) + kc*64 + kk4*4);
                    a4[i][0]=t.x; a4[i][1]=t.y; a4[i][2]=t.z; a4[i][3]=t.w;
                }
                #pragma unroll
                for (int j = 0; j < 4; j++) {
                    u64t wv = *reinterpret_cast<const u64t*>(wbuf + (kk4*4+j)*64 + lane*2);
                    #pragma unroll
                    for (int i = 0; i < 8; i++) {
                        u64t ad = pk2(a4[i][j], a4[i][j]);
                        ha2[i] = fm2(ad, wv, ha2[i]);
                    }
                }
            }
        }
        #pragma unroll
        for (int i = 0; i < 8; i++) {
            int row = r0+i;
            if (row < NJ) {
                float h0, h1; up2(ha2[i], h0, h1);
                float g0 = 0.5f*h0*(1.0f + erff(h0*0.70710678118654752f));
                float g1 = 0.5f*h1*(1.0f + erff(h1*0.70710678118654752f));
                *reinterpret_cast<float2*>(ao + row*64 + lane*2) = make_float2(g0, g1);
            }
        }
        __syncwarp();
        #pragma unroll
        for (int i = 0; i < 11; i++) {
            int idx = tid + i*384;
            if (idx < 4096) st[i] = fc2_w[L*8192 + idx];
        }
        #pragma unroll 1
        for (int kc = 0; kc < 2; kc++) {
            __syncthreads();
            #pragma unroll
            for (int i = 0; i < 11; i++) {
                int idx = tid + i*384;
                if (idx < 4096) wbuf[idx] = st[i];
            }
            __syncthreads();
            if (kc < 1) {
                #pragma unroll
                for (int i = 0; i < 11; i++) {
                    int idx = tid + i*384;
                    if (idx < 4096) st[i] = fc2_w[L*8192 + 4096 + idx];
                }
            }
            u64t xa[8], xb[8];
            #pragma unroll
            for (int i = 0; i < 8; i++) { xa[i]=pk2(x[i][0],x[i][1]); xb[i]=pk2(x[i][2],x[i][3]); }
            #pragma unroll 1
            for (int kk4 = 0; kk4 < 8; kk4++) {
                float a4[8][4];
                #pragma unroll
                for (int i = 0; i < 8; i++) {
                    int row = r0+i; row = row < NJ ? row : (NJ-1);
                    float4 t = *reinterpret_cast<float4*>(ao + row*64 + kc*32 + kk4*4);
                    a4[i][0]=t.x; a4[i][1]=t.y; a4[i][2]=t.z; a4[i][3]=t.w;
                }
                #pragma unroll
                for (int j = 0; j < 4; j++) {
                    ulonglong2 Wv = *reinterpret_cast<const ulonglong2*>(wbuf + (kk4*4+j)*128 + c0);
                    #pragma unroll
                    for (int i = 0; i < 8; i++) {
                        u64t ad = pk2(a4[i][j], a4[i][j]);
                        xa[i] = fm2(ad, Wv.x, xa[i]);
                        xb[i] = fm2(ad, Wv.y, xb[i]);
                    }
                }
            }
            #pragma unroll
            for (int i = 0; i < 8; i++) { up2(xa[i],x[i][0],x[i][1]); up2(xb[i],x[i][2],x[i][3]); }
        }
        {
            float4 fb = *reinterpret_cast<const float4*>(fc2_b + L*128 + c0);
            #pragma unroll
            for (int i = 0; i < 8; i++) {
                x[i][0]+=fb.x; x[i][1]+=fb.y; x[i][2]+=fb.z; x[i][3]+=fb.w;
            }
        }
    }

    if (eb < NB) {
        #pragma unroll
        for (int i = 0; i < 8; i++) {
            int row = r0+i;
            if (row < NJ)
                *reinterpret_cast<float4*>(out + base + row*128 + c0) =
                    make_float4(x[i][0], x[i][1], x[i][2], x[i][3]);
        }
    }
}

extern "C" void kernel_launch(void* const* d_in, const int* in_sizes, int n_in,
                              void* d_out, int out_size) {
    (void)in_sizes; (void)n_in; (void)out_size;
    const float** p = (const float**)d_in;
    cudaFuncSetAttribute(jr_kernel, cudaFuncAttributeMaxDynamicSharedMemorySize,
                         SMEM_BYTES);
    jr_kernel<<<(NB + EPC - 1)/EPC, NTHR, SMEM_BYTES>>>(
        p[0], p[1], p[2], p[3], p[4], p[5], p[6], p[7], p[8], p[9],
        p[10], p[11], p[12], p[13], p[14], p[15], p[16], p[17], p[18], p[19],
        (float*)d_out);
}

// round 13
// speedup vs baseline: 1.6645x; 1.0292x over previous
#include <cuda_runtime.h>
#define NB 16384
#define NJ 15
#define NDEPTH 6
#define EPC 6
#define NTHR 384
#define RO(r) ((r)*128 + (((r)>>3)<<3))
#define RNOFF 2064
#define AOOFF 4128
#define QSOFF 6112
#define ESTRIDE 7552
#define WBUF_OFF (EPC*ESTRIDE)
#define CBUF_OFF (WBUF_OFF+6912)
#define LN2C_OFF (CBUF_OFF+144)
#define BFOLD_OFF (LN2C_OFF+128)
#define SMEM_FLOATS (BFOLD_OFF+384)
#define SMEM_BYTES (SMEM_FLOATS*4)

__device__ float g_bfold[NDEPTH*384];

typedef unsigned long long u64t;
__device__ __forceinline__ u64t pk2(float lo, float hi) {
    u64t r; asm("mov.b64 %0, {%1,%2};" : "=l"(r) : "f"(lo), "f"(hi)); return r;
}
__device__ __forceinline__ void up2(u64t p, float& lo, float& hi) {
    asm("mov.b64 {%0,%1}, %2;" : "=f"(lo), "=f"(hi) : "l"(p));
}
__device__ __forceinline__ u64t fm2(u64t a, u64t b, u64t c) {
    u64t d; asm("fma.rn.f32x2 %0, %1, %2, %3;" : "=l"(d) : "l"(a), "l"(b), "l"(c)); return d;
}
__device__ __forceinline__ u64t ml2(u64t a, u64t b) {
    u64t d; asm("mul.rn.f32x2 %0, %1, %2;" : "=l"(d) : "l"(a), "l"(b)); return d;
}
__device__ __forceinline__ void row_stats4(float v0, float v1, float v2, float v3,
                                           float& mu, float& inv) {
    float s = v0+v1+v2+v3, ss = v0*v0+v1*v1+v2*v2+v3*v3;
    #pragma unroll
    for (int off = 16; off > 0; off >>= 1) {
        s  += __shfl_xor_sync(0xffffffffu, s,  off);
        ss += __shfl_xor_sync(0xffffffffu, ss, off);
    }
    mu = s * (1.0f/128.0f);
    inv = rsqrtf(ss * (1.0f/128.0f) - mu*mu + 1e-5f);
}

__global__ void bfold_prep(const float* __restrict__ Iqk_b,
                           const float* __restrict__ Iqk_w,
                           const float* __restrict__ ln2_b) {
    int L = blockIdx.x, c = threadIdx.x;
    float a = Iqk_b[L*384 + c];
    const float* wc = Iqk_w + L*49152 + c;
    const float* b2 = ln2_b + L*128;
    #pragma unroll 8
    for (int k = 0; k < 128; k++)
        a = fmaf(__ldg(b2+k), __ldg(wc + k*384), a);
    g_bfold[L*384 + c] = a;
}

__global__ __launch_bounds__(NTHR, 1)
void jr_kernel(const float* __restrict__ joint, const float* __restrict__ rel,
               const float* __restrict__ Jqkv_w, const float* __restrict__ Jqkv_b,
               const float* __restrict__ Iqk_w,  const float* __restrict__ Iqk_b,
               const float* __restrict__ Iconv_w,const float* __restrict__ Iconv_b,
               const float* __restrict__ proj_w, const float* __restrict__ proj_b,
               const float* __restrict__ ln1_w,  const float* __restrict__ ln1_b,
               const float* __restrict__ ln2_w,  const float* __restrict__ ln2_b,
               const float* __restrict__ ln3_w,  const float* __restrict__ ln3_b,
               const float* __restrict__ fc1_w,  const float* __restrict__ fc1_b,
               const float* __restrict__ fc2_w,  const float* __restrict__ fc2_b,
               float* __restrict__ out)
{
    extern __shared__ float sm[];
    const int tid = threadIdx.x, wid = tid>>5, elem = wid>>1, ws = wid&1;
    const int lane = tid&31, c0 = lane*4, r0 = ws*8;
    const int rg = lane>>4, cg = lane&15, sd = cg>>3, dd = cg&7;
    // group staging constants: group g = ws stages its own head slot
    const int tg  = elem*32 + lane;          // 0..191 within group
    const int col = tg % 48;
    const int kk0 = tg / 48;                 // 0..3
    const int sI  = col >= 24;
    const int c2  = col - sI*24;
    const int gcb0 = (c2>>3)*128 + ws*8 + (c2&7);
    const int ssm0 = ws*3456 + col*36 + kk0;

    float* jn  = sm + elem*ESTRIDE;
    float* rn  = jn + RNOFF;
    float* ao  = jn + AOOFF;
    float* qsw = jn + QSOFF + ws*720;
    float* wbuf  = sm + WBUF_OFF;
    float* cbuf  = sm + CBUF_OFF;
    float* ln2c  = sm + LN2C_OFF;
    float* bfold = sm + BFOLD_OFF;

    const int eb = blockIdx.x*EPC + elem;
    const int e  = eb < NB ? eb : (NB-1);
    const long base = (long)e * (NJ*128);
    float st[11];

    float x[8][4];
    #pragma unroll
    for (int i = 0; i < 8; i++) {
        int row = r0+i, grow = row < NJ ? row : (NJ-1);
        float4 v = *reinterpret_cast<const float4*>(joint + base + grow*128 + c0);
        x[i][0]=v.x; x[i][1]=v.y; x[i][2]=v.z; x[i][3]=v.w;
    }
    #pragma unroll
    for (int i = 0; i < 8; i++) {
        int row = r0+i, grow = row < NJ ? row : (NJ-1);
        float4 v = *reinterpret_cast<const float4*>(rel + base + grow*128 + c0);
        float mu, inv;
        row_stats4(v.x, v.y, v.z, v.w, mu, inv);
        if (row < NJ) {
            float4 o;
            o.x=(v.x-mu)*inv; o.y=(v.y-mu)*inv; o.z=(v.z-mu)*inv; o.w=(v.w-mu)*inv;
            *reinterpret_cast<float4*>(rn + RO(row) + c0) = o;
        }
    }
    {
        float4 z = make_float4(0.f,0.f,0.f,0.f);
        *reinterpret_cast<float4*>(jn + RO(15) + c0) = z;
        *reinterpret_cast<float4*>(rn + RO(15) + c0) = z;
    }

    #pragma unroll 1
    for (int L = 0; L < NDEPTH; L++) {
        const float* Jw = Jqkv_w + L*49152;
        const float* Jb = Jqkv_b + L*384;
        const float* Iw = Iqk_w  + L*49152;
        const float* Pw = proj_w + L*16384;
        const float* Sw = sI ? Iw : Jw;

        __syncthreads();
        if (tid < 128) {
            int d2 = tid>>4, m = tid&15;
            cbuf[tid] = (m < NJ) ? Iconv_w[L*(8*NJ) + d2*NJ + m] : 0.f;
            ln2c[tid] = ln2_w[L*128 + tid];
        } else if (tid < 144) {
            int m = tid-128;
            cbuf[128+m] = (m < NJ) ? Iconv_b[L*NJ + m] : 0.f;
        }
        if (tid < 384) bfold[tid] = g_bfold[L*384 + tid];
        {
            float4 w1 = *reinterpret_cast<const float4*>(ln1_w + L*128 + c0);
            float4 b1 = *reinterpret_cast<const float4*>(ln1_b + L*128 + c0);
            #pragma unroll
            for (int i = 0; i < 8; i++) {
                float mu, inv;
                row_stats4(x[i][0], x[i][1], x[i][2], x[i][3], mu, inv);
                int row = r0+i;
                if (row < NJ) {
                    float4 o;
                    o.x = fmaf((x[i][0]-mu)*inv, w1.x, b1.x);
                    o.y = fmaf((x[i][1]-mu)*inv, w1.y, b1.y);
                    o.z = fmaf((x[i][2]-mu)*inv, w1.z, b1.z);
                    o.w = fmaf((x[i][3]-mu)*inv, w1.w, b1.w);
                    *reinterpret_cast<float4*>(jn + RO(row) + c0) = o;
                }
            }
        }
        __syncthreads();

        // prefetch attention chunk (r=0,q=0): 8 floats/thread
        {
            const float* gp = Sw + gcb0 + kk0*384;
            const float* lp = ln2c + kk0;
            #pragma unroll
            for (int i = 0; i < 8; i++)
                st[i] = sI ? gp[i*1536]*lp[4*i] : gp[i*1536];
        }
        #pragma unroll 1
        for (int r = 0; r < 8; r++) {
            const int h = r*2 + ws;
            u64t acc[3][8];
            #pragma unroll
            for (int mt = 0; mt < 3; mt++) {
                float bv = sd ? bfold[mt*128 + h*8 + dd] : __ldg(Jb + mt*128 + h*8 + dd);
                #pragma unroll
                for (int i = 0; i < 8; i++) acc[mt][i] = pk2(bv, 0.f);
            }
            #pragma unroll 1
            for (int q = 0; q < 4; q++) {
                const int p = q & 1;
                #pragma unroll
                for (int i = 0; i < 8; i++) wbuf[ssm0 + p*1728 + 4*i] = st[i];
                asm volatile("bar.sync %0, %1;" :: "r"(2+ws), "r"(192) : "memory");
                {
                    int nr = r, nq = q + 1;
                    if (nq == 4) { nq = 0; nr++; }
                    if (nr < 8) {
                        const float* gp = Sw + gcb0 + nr*16 + (nq*32 + kk0)*384;
                        const float* lp = ln2c + nq*32 + kk0;
                        #pragma unroll
                        for (int i = 0; i < 8; i++)
                            st[i] = sI ? gp[i*1536]*lp[4*i] : gp[i*1536];
                    }
                }
                const float* ap  = jn + sd*RNOFF + rg*1032 + q*32;
                const float* w0p = wbuf + ws*3456 + p*1728 + (sd*24 + dd)*36;
                const float* w1p = w0p + 288;
                const float* w2p = w0p + 576;
                #pragma unroll 4
                for (int k = 0; k < 32; k += 4) {
                    ulonglong2 W0 = *reinterpret_cast<const ulonglong2*>(w0p + k);
                    ulonglong2 W1 = *reinterpret_cast<const ulonglong2*>(w1p + k);
                    ulonglong2 W2 = *reinterpret_cast<const ulonglong2*>(w2p + k);
                    #pragma unroll
                    for (int i = 0; i < 8; i++) {
                        ulonglong2 A = *reinterpret_cast<const ulonglong2*>(ap + i*128 + k);
                        acc[0][i] = fm2(A.x, W0.x, acc[0][i]);
                        acc[0][i] = fm2(A.y, W0.y, acc[0][i]);
                        acc[1][i] = fm2(A.x, W1.x, acc[1][i]);
                        acc[1][i] = fm2(A.y, W1.y, acc[1][i]);
                        acc[2][i] = fm2(A.x, W2.x, acc[2][i]);
                        acc[2][i] = fm2(A.y, W2.y, acc[2][i]);
                    }
                }
            }
            #pragma unroll
            for (int mt = 0; mt < 3; mt++) {
                #pragma unroll
                for (int i = 0; i < 8; i++) {
                    int row = rg*8 + i;
                    if (row < NJ) {
                        float lo, hi; up2(acc[mt][i], lo, hi);
                        qsw[(sd*3+mt)*120 + row*8 + dd] = lo + hi;
                    }
                }
            }
            __syncwarp();
            {
                const int pr = lane >> 4;
                const int n  = lane & 15;
                if (n < NJ) {
                    float sc[NJ];
                    if (pr == 0) {
                        ulonglong2 Q0 = *reinterpret_cast<const ulonglong2*>(qsw + 0*120 + n*8);
                        ulonglong2 Q1 = *reinterpret_cast<const ulonglong2*>(qsw + 0*120 + n*8 + 4);
                        #pragma unroll
                        for (int m = 0; m < NJ; m++) {
                            ulonglong2 K0 = *reinterpret_cast<const ulonglong2*>(qsw + 1*120 + m*8);
                            ulonglong2 K1 = *reinterpret_cast<const ulonglong2*>(qsw + 1*120 + m*8 + 4);
                            u64t t2 = ml2(Q0.x, K0.x);
                            t2 = fm2(Q0.y, K0.y, t2);
                            t2 = fm2(Q1.x, K1.x, t2);
                            t2 = fm2(Q1.y, K1.y, t2);
                            float lo, hi; up2(t2, lo, hi);
                            sc[m] = lo + hi;
                        }
                    } else {
                        ulonglong2 U0 = *reinterpret_cast<const ulonglong2*>(qsw + 3*120 + n*8);
                        ulonglong2 U1 = *reinterpret_cast<const ulonglong2*>(qsw + 3*120 + n*8 + 4);
                        float iv[8];
                        {
                            float4 v0 = *reinterpret_cast<float4*>(qsw + 5*120 + n*8);
                            float4 v1 = *reinterpret_cast<float4*>(qsw + 5*120 + n*8 + 4);
                            iv[0]=v0.x; iv[1]=v0.y; iv[2]=v0.z; iv[3]=v0.w;
                            iv[4]=v1.x; iv[5]=v1.y; iv[6]=v1.z; iv[7]=v1.w;
                        }
                        #pragma unroll
                        for (int m = 0; m < NJ; m++) {
                            ulonglong2 I0 = *reinterpret_cast<const ulonglong2*>(qsw + 4*120 + m*8);
                            ulonglong2 I1 = *reinterpret_cast<const ulonglong2*>(qsw + 4*120 + m*8 + 4);
                            u64t t2 = ml2(U0.x, I0.x);
                            t2 = fm2(U0.y, I0.y, t2);
                            t2 = fm2(U1.x, I1.x, t2);
                            t2 = fm2(U1.y, I1.y, t2);
                            float lo, hi; up2(t2, lo, hi);
                            float t = cbuf[128+m];
                            #pragma unroll
                            for (int d3 = 0; d3 < 8; d3++)
                                t = fmaf(iv[d3], cbuf[d3*16 + m], t);
                            sc[m] = t + lo + hi;
                        }
                    }
                    #pragma unroll
                    for (int m = 0; m < NJ; m++) {
                        float o2 = __shfl_xor_sync(0x7fff7fffu, sc[m], 16);
                        sc[m] = (sc[m] + o2) * 0.6f;
                    }
                    float mx = sc[0];
                    #pragma unroll
                    for (int m = 1; m < NJ; m++) mx = fmaxf(mx, sc[m]);
                    float sum = 0.f;
                    #pragma unroll
                    for (int m = 0; m < NJ; m++) { sc[m] = __expf(sc[m]-mx); sum += sc[m]; }
                    float rs = 1.0f/sum;
                    u64t o0 = 0ull, o1 = 0ull;
                    const float* jvh = qsw + 2*120 + pr*4;
                    #pragma unroll
                    for (int m = 0; m < NJ; m++) {
                        float pm = sc[m]*rs;
                        u64t pm2 = pk2(pm, pm);
                        ulonglong2 Jh = *reinterpret_cast<const ulonglong2*>(jvh + m*8);
                        o0 = fm2(pm2, Jh.x, o0);
                        o1 = fm2(pm2, Jh.y, o1);
                    }
                    *reinterpret_cast<ulonglong2*>(ao + n*132 + h*8 + pr*4) =
                        make_ulonglong2(o0, o1);
                }
            }
        }

        // proj
        #pragma unroll
        for (int i = 0; i < 11; i++) {
            int idx = tid + i*384;
            if (idx < 4096) st[i] = Pw[idx];
        }
        #pragma unroll 1
        for (int kc = 0; kc < 4; kc++) {
            __syncthreads();
            #pragma unroll
            for (int i = 0; i < 11; i++) {
                int idx = tid + i*384;
                if (idx < 4096) wbuf[idx] = st[i];
            }
            __syncthreads();
            if (kc < 3) {
                #pragma unroll
                for (int i = 0; i < 11; i++) {
                    int idx = tid + i*384;
                    if (idx < 4096) st[i] = Pw[(kc+1)*4096 + idx];
                }
            }
            u64t xa[8], xb[8];
            #pragma unroll
            for (int i = 0; i < 8; i++) { xa[i]=pk2(x[i][0],x[i][1]); xb[i]=pk2(x[i][2],x[i][3]); }
            #pragma unroll 1
            for (int kk4 = 0; kk4 < 8; kk4++) {
                float a4[8][4];
                #pragma unroll
                for (int i = 0; i < 8; i++) {
                    int row = r0+i; row = row < NJ ? row : (NJ-1);
                    float4 t = *reinterpret_cast<float4*>(ao + row*132 + kc*32 + kk4*4);
                    a4[i][0]=t.x; a4[i][1]=t.y; a4[i][2]=t.z; a4[i][3]=t.w;
                }
                #pragma unroll
                for (int j = 0; j < 4; j++) {
                    ulonglong2 Wv = *reinterpret_cast<const ulonglong2*>(wbuf + (kk4*4+j)*128 + c0);
                    #pragma unroll
                    for (int i = 0; i < 8; i++) {
                        u64t ad = pk2(a4[i][j], a4[i][j]);
                        xa[i] = fm2(ad, Wv.x, xa[i]);
                        xb[i] = fm2(ad, Wv.y, xb[i]);
                    }
                }
            }
            #pragma unroll
            for (int i = 0; i < 8; i++) { up2(xa[i],x[i][0],x[i][1]); up2(xb[i],x[i][2],x[i][3]); }
        }
        {
            float4 pb = *reinterpret_cast<const float4*>(proj_b + L*128 + c0);
            #pragma unroll
            for (int i = 0; i < 8; i++) {
                x[i][0]+=pb.x; x[i][1]+=pb.y; x[i][2]+=pb.z; x[i][3]+=pb.w;
            }
        }
        {
            float4 w3 = *reinterpret_cast<const float4*>(ln3_w + L*128 + c0);
            float4 b3 = *reinterpret_cast<const float4*>(ln3_b + L*128 + c0);
            #pragma unroll
            for (int i = 0; i < 8; i++) {
                float mu, inv;
                row_stats4(x[i][0], x[i][1], x[i][2], x[i][3], mu, inv);
                int row = r0+i;
                if (row < NJ) {
                    float4 o;
                    o.x = fmaf((x[i][0]-mu)*inv, w3.x, b3.x);
                    o.y = fmaf((x[i][1]-mu)*inv, w3.y, b3.y);
                    o.z = fmaf((x[i][2]-mu)*inv, w3.z, b3.z);
                    o.w = fmaf((x[i][3]-mu)*inv, w3.w, b3.w);
                    *reinterpret_cast<float4*>(jn + RO(row) + c0) = o;
                }
            }
        }
        u64t ha2[8];
        {
            float2 fb = *reinterpret_cast<const float2*>(fc1_b + L*64 + lane*2);
            #pragma unroll
            for (int i = 0; i < 8; i++) ha2[i] = pk2(fb.x, fb.y);
        }
        #pragma unroll
        for (int i = 0; i < 11; i++) {
            int idx = tid + i*384;
            if (idx < 4096) st[i] = fc1_w[L*8192 + idx];
        }
        #pragma unroll 1
        for (int kc = 0; kc < 2; kc++) {
            __syncthreads();
            #pragma unroll
            for (int i = 0; i < 11; i++) {
                int idx = tid + i*384;
                if (idx < 4096) wbuf[idx] = st[i];
            }
            __syncthreads();
            if (kc < 1) {
                #pragma unroll
                for (int i = 0; i < 11; i++) {
                    int idx = tid + i*384;
                    if (idx < 4096) st[i] = fc1_w[L*8192 + 4096 + idx];
                }
            }
            #pragma unroll 1
            for (int kk4 = 0; kk4 < 16; kk4++) {
                float a4[8][4];
                #pragma unroll
                for (int i = 0; i < 8; i++) {
                    int row = r0+i; row = row < NJ ? row : (NJ-1);
                    float4 t = *reinterpret_cast<float4*>(jn + RO(row) + kc*64 + kk4*4);
                    a4[i][0]=t.x; a4[i][1]=t.y; a4[i][2]=t.z; a4[i][3]=t.w;
                }
                #pragma unroll
                for (int j = 0; j < 4; j++) {
                    u64t wv = *reinterpret_cast<const u64t*>(wbuf + (kk4*4+j)*64 + lane*2);
                    #pragma unroll
                    for (int i = 0; i < 8; i++) {
                        u64t ad = pk2(a4[i][j], a4[i][j]);
                        ha2[i] = fm2(ad, wv, ha2[i]);
                    }
                }
            }
        }
        #pragma unroll
        for (int i = 0; i < 8; i++) {
            int row = r0+i;
            if (row < NJ) {
                float h0, h1; up2(ha2[i], h0, h1);
                float g0 = 0.5f*h0*(1.0f + erff(h0*0.70710678118654752f));
                float g1 = 0.5f*h1*(1.0f + erff(h1*0.70710678118654752f));
                *reinterpret_cast<float2*>(ao + row*64 + lane*2) = make_float2(g0, g1);
            }
        }
        __syncwarp();
        #pragma unroll
        for (int i = 0; i < 11; i++) {
            int idx = tid + i*384;
            if (idx < 4096) st[i] = fc2_w[L*8192 + idx];
        }
        #pragma unroll 1
        for (int kc = 0; kc < 2; kc++) {
            __syncthreads();
            #pragma unroll
            for (int i = 0; i < 11; i++) {
                int idx = tid + i*384;
                if (idx < 4096) wbuf[idx] = st[i];
            }
            __syncthreads();
            if (kc < 1) {
                #pragma unroll
                for (int i = 0; i < 11; i++) {
                    int idx = tid + i*384;
                    if (idx < 4096) st[i] = fc2_w[L*8192 + 4096 + idx];
                }
            }
            u64t xa[8], xb[8];
            #pragma unroll
            for (int i = 0; i < 8; i++) { xa[i]=pk2(x[i][0],x[i][1]); xb[i]=pk2(x[i][2],x[i][3]); }
            #pragma unroll 1
            for (int kk4 = 0; kk4 < 8; kk4++) {
                float a4[8][4];
                #pragma unroll
                for (int i = 0; i < 8; i++) {
                    int row = r0+i; row = row < NJ ? row : (NJ-1);
                    float4 t = *reinterpret_cast<float4*>(ao + row*64 + kc*32 + kk4*4);
                    a4[i][0]=t.x; a4[i][1]=t.y; a4[i][2]=t.z; a4[i][3]=t.w;
                }
                #pragma unroll
                for (int j = 0; j < 4; j++) {
                    ulonglong2 Wv = *reinterpret_cast<const ulonglong2*>(wbuf + (kk4*4+j)*128 + c0);
                    #pragma unroll
                    for (int i = 0; i < 8; i++) {
                        u64t ad = pk2(a4[i][j], a4[i][j]);
                        xa[i] = fm2(ad, Wv.x, xa[i]);
                        xb[i] = fm2(ad, Wv.y, xb[i]);
                    }
                }
            }
            #pragma unroll
            for (int i = 0; i < 8; i++) { up2(xa[i],x[i][0],x[i][1]); up2(xb[i],x[i][2],x[i][3]); }
        }
        {
            float4 fb = *reinterpret_cast<const float4*>(fc2_b + L*128 + c0);
            #pragma unroll
            for (int i = 0; i < 8; i++) {
                x[i][0]+=fb.x; x[i][1]+=fb.y; x[i][2]+=fb.z; x[i][3]+=fb.w;
            }
        }
    }

    if (eb < NB) {
        #pragma unroll
        for (int i = 0; i < 8; i++) {
            int row = r0+i;
            if (row < NJ)
                *reinterpret_cast<float4*>(out + base + row*128 + c0) =
                    make_float4(x[i][0], x[i][1], x[i][2], x[i][3]);
        }
    }
}

extern "C" void kernel_launch(void* const* d_in, const int* in_sizes, int n_in,
                              void* d_out, int out_size) {
    (void)in_sizes; (void)n_in; (void)out_size;
    const float** p = (const float**)d_in;
    bfold_prep<<<NDEPTH, 384>>>(p[5], p[4], p[13]);
    cudaFuncSetAttribute(jr_kernel, cudaFuncAttributeMaxDynamicSharedMemorySize,
                         SMEM_BYTES);
    jr_kernel<<<(NB + EPC - 1)/EPC, NTHR, SMEM_BYTES>>>(
        p[0], p[1], p[2], p[3], p[4], p[5], p[6], p[7], p[8], p[9],
        p[10], p[11], p[12], p[13], p[14], p[15], p[16], p[17], p[18], p[19],
        (float*)d_out);
}

// round 14
// speedup vs baseline: 1.6661x; 1.0009x over previous
#include <cuda_runtime.h>
#define NB 16384
#define NJ 15
#define NDEPTH 6
#define EPC 6
#define NTHR 384
#define RO(r) ((r)*128 + (((r)>>3)<<3))
#define RNOFF 2064
#define AOOFF 4128
#define QSOFF 6112
#define ESTRIDE 7552
#define WBUF_OFF (EPC*ESTRIDE)
#define CBUF_OFF (WBUF_OFF+8192)
#define LN2C_OFF (CBUF_OFF+144)
#define BFOLD_OFF (LN2C_OFF+128)
#define SMEM_FLOATS (BFOLD_OFF+384)
#define SMEM_BYTES (SMEM_FLOATS*4)

__device__ float g_bfold[NDEPTH*384];

typedef unsigned long long u64t;
__device__ __forceinline__ u64t pk2(float lo, float hi) {
    u64t r; asm("mov.b64 %0, {%1,%2};" : "=l"(r) : "f"(lo), "f"(hi)); return r;
}
__device__ __forceinline__ void up2(u64t p, float& lo, float& hi) {
    asm("mov.b64 {%0,%1}, %2;" : "=f"(lo), "=f"(hi) : "l"(p));
}
__device__ __forceinline__ u64t fm2(u64t a, u64t b, u64t c) {
    u64t d; asm("fma.rn.f32x2 %0, %1, %2, %3;" : "=l"(d) : "l"(a), "l"(b), "l"(c)); return d;
}
__device__ __forceinline__ u64t ml2(u64t a, u64t b) {
    u64t d; asm("mul.rn.f32x2 %0, %1, %2;" : "=l"(d) : "l"(a), "l"(b)); return d;
}
__device__ __forceinline__ void row_stats4(float v0, float v1, float v2, float v3,
                                           float& mu, float& inv) {
    float s = v0+v1+v2+v3, ss = v0*v0+v1*v1+v2*v2+v3*v3;
    #pragma unroll
    for (int off = 16; off > 0; off >>= 1) {
        s  += __shfl_xor_sync(0xffffffffu, s,  off);
        ss += __shfl_xor_sync(0xffffffffu, ss, off);
    }
    mu = s * (1.0f/128.0f);
    inv = rsqrtf(ss * (1.0f/128.0f) - mu*mu + 1e-5f);
}

__global__ void bfold_prep(const float* __restrict__ Iqk_b,
                           const float* __restrict__ Iqk_w,
                           const float* __restrict__ ln2_b) {
    int L = blockIdx.x, c = threadIdx.x;
    float a = Iqk_b[L*384 + c];
    const float* wc = Iqk_w + L*49152 + c;
    const float* b2 = ln2_b + L*128;
    #pragma unroll 8
    for (int k = 0; k < 128; k++)
        a = fmaf(__ldg(b2+k), __ldg(wc + k*384), a);
    g_bfold[L*384 + c] = a;
}

__global__ __launch_bounds__(NTHR, 1)
void jr_kernel(const float* __restrict__ joint, const float* __restrict__ rel,
               const float* __restrict__ Jqkv_w, const float* __restrict__ Jqkv_b,
               const float* __restrict__ Iqk_w,  const float* __restrict__ Iqk_b,
               const float* __restrict__ Iconv_w,const float* __restrict__ Iconv_b,
               const float* __restrict__ proj_w, const float* __restrict__ proj_b,
               const float* __restrict__ ln1_w,  const float* __restrict__ ln1_b,
               const float* __restrict__ ln2_w,  const float* __restrict__ ln2_b,
               const float* __restrict__ ln3_w,  const float* __restrict__ ln3_b,
               const float* __restrict__ fc1_w,  const float* __restrict__ fc1_b,
               const float* __restrict__ fc2_w,  const float* __restrict__ fc2_b,
               float* __restrict__ out)
{
    extern __shared__ float sm[];
    const int tid = threadIdx.x, wid = tid>>5, elem = wid>>1, ws = wid&1;
    const int lane = tid&31, c0 = lane*4, r0 = ws*8;
    const int rg = lane>>4, cg = lane&15, sd = cg>>3, dd = cg&7;
    const int tg  = elem*32 + lane;
    const int col = tg % 48;
    const int kk0 = tg / 48;
    const int sI  = col >= 24;
    const int c2  = col - sI*24;
    const int gcb0 = (c2>>3)*128 + ws*8 + (c2&7);
    const int ssm0 = ws*3456 + col*36 + kk0;

    float* jn  = sm + elem*ESTRIDE;
    float* rn  = jn + RNOFF;
    float* ao  = jn + AOOFF;
    float* qsw = jn + QSOFF + ws*720;
    float* wbuf  = sm + WBUF_OFF;
    float* cbuf  = sm + CBUF_OFF;
    float* ln2c  = sm + LN2C_OFF;
    float* bfold = sm + BFOLD_OFF;

    const int eb = blockIdx.x*EPC + elem;
    const int e  = eb < NB ? eb : (NB-1);
    const long base = (long)e * (NJ*128);
    float st[11];

    float x[8][4];
    #pragma unroll
    for (int i = 0; i < 8; i++) {
        int row = r0+i, grow = row < NJ ? row : (NJ-1);
        float4 v = *reinterpret_cast<const float4*>(joint + base + grow*128 + c0);
        x[i][0]=v.x; x[i][1]=v.y; x[i][2]=v.z; x[i][3]=v.w;
    }
    #pragma unroll
    for (int i = 0; i < 8; i++) {
        int row = r0+i, grow = row < NJ ? row : (NJ-1);
        float4 v = *reinterpret_cast<const float4*>(rel + base + grow*128 + c0);
        float mu, inv;
        row_stats4(v.x, v.y, v.z, v.w, mu, inv);
        if (row < NJ) {
            float4 o;
            o.x=(v.x-mu)*inv; o.y=(v.y-mu)*inv; o.z=(v.z-mu)*inv; o.w=(v.w-mu)*inv;
            *reinterpret_cast<float4*>(rn + RO(row) + c0) = o;
        }
    }
    {
        float4 z = make_float4(0.f,0.f,0.f,0.f);
        *reinterpret_cast<float4*>(jn + RO(15) + c0) = z;
        *reinterpret_cast<float4*>(rn + RO(15) + c0) = z;
    }

    #pragma unroll 1
    for (int L = 0; L < NDEPTH; L++) {
        const float* Jw = Jqkv_w + L*49152;
        const float* Jb = Jqkv_b + L*384;
        const float* Iw = Iqk_w  + L*49152;
        const float* Pw = proj_w + L*16384;
        const float* Sw = sI ? Iw : Jw;

        __syncthreads();
        if (tid < 128) {
            int d2 = tid>>4, m = tid&15;
            cbuf[tid] = (m < NJ) ? Iconv_w[L*(8*NJ) + d2*NJ + m] : 0.f;
            ln2c[tid] = ln2_w[L*128 + tid];
        } else if (tid < 144) {
            int m = tid-128;
            cbuf[128+m] = (m < NJ) ? Iconv_b[L*NJ + m] : 0.f;
        }
        if (tid < 384) bfold[tid] = g_bfold[L*384 + tid];
        {
            float4 w1 = *reinterpret_cast<const float4*>(ln1_w + L*128 + c0);
            float4 b1 = *reinterpret_cast<const float4*>(ln1_b + L*128 + c0);
            #pragma unroll
            for (int i = 0; i < 8; i++) {
                float mu, inv;
                row_stats4(x[i][0], x[i][1], x[i][2], x[i][3], mu, inv);
                int row = r0+i;
                if (row < NJ) {
                    float4 o;
                    o.x = fmaf((x[i][0]-mu)*inv, w1.x, b1.x);
                    o.y = fmaf((x[i][1]-mu)*inv, w1.y, b1.y);
                    o.z = fmaf((x[i][2]-mu)*inv, w1.z, b1.z);
                    o.w = fmaf((x[i][3]-mu)*inv, w1.w, b1.w);
                    *reinterpret_cast<float4*>(jn + RO(row) + c0) = o;
                }
            }
        }
        __syncthreads();

        // prefetch attention chunk (r=0,q=0)
        {
            const float* gp = Sw + gcb0 + kk0*384;
            const float* lp = ln2c + kk0;
            #pragma unroll
            for (int i = 0; i < 8; i++)
                st[i] = sI ? gp[i*1536]*lp[4*i] : gp[i*1536];
        }
        #pragma unroll 1
        for (int r = 0; r < 8; r++) {
            const int h = r*2 + ws;
            u64t acc[3][8];
            #pragma unroll
            for (int mt = 0; mt < 3; mt++) {
                float bv = sd ? bfold[mt*128 + h*8 + dd] : __ldg(Jb + mt*128 + h*8 + dd);
                #pragma unroll
                for (int i = 0; i < 8; i++) acc[mt][i] = pk2(bv, 0.f);
            }
            #pragma unroll 1
            for (int q = 0; q < 4; q++) {
                const int p = q & 1;
                #pragma unroll
                for (int i = 0; i < 8; i++) wbuf[ssm0 + p*1728 + 4*i] = st[i];
                asm volatile("bar.sync %0, %1;" :: "r"(2+ws), "r"(192) : "memory");
                {
                    int nr = r, nq = q + 1;
                    if (nq == 4) { nq = 0; nr++; }
                    if (nr < 8) {
                        const float* gp = Sw + gcb0 + nr*16 + (nq*32 + kk0)*384;
                        const float* lp = ln2c + nq*32 + kk0;
                        #pragma unroll
                        for (int i = 0; i < 8; i++)
                            st[i] = sI ? gp[i*1536]*lp[4*i] : gp[i*1536];
                    }
                }
                const float* ap  = jn + sd*RNOFF + rg*1032 + q*32;
                const float* w0p = wbuf + ws*3456 + p*1728 + (sd*24 + dd)*36;
                const float* w1p = w0p + 288;
                const float* w2p = w0p + 576;
                #pragma unroll 4
                for (int k = 0; k < 32; k += 4) {
                    ulonglong2 W0 = *reinterpret_cast<const ulonglong2*>(w0p + k);
                    ulonglong2 W1 = *reinterpret_cast<const ulonglong2*>(w1p + k);
                    ulonglong2 W2 = *reinterpret_cast<const ulonglong2*>(w2p + k);
                    #pragma unroll
                    for (int i = 0; i < 8; i++) {
                        ulonglong2 A = *reinterpret_cast<const ulonglong2*>(ap + i*128 + k);
                        acc[0][i] = fm2(A.x, W0.x, acc[0][i]);
                        acc[0][i] = fm2(A.y, W0.y, acc[0][i]);
                        acc[1][i] = fm2(A.x, W1.x, acc[1][i]);
                        acc[1][i] = fm2(A.y, W1.y, acc[1][i]);
                        acc[2][i] = fm2(A.x, W2.x, acc[2][i]);
                        acc[2][i] = fm2(A.y, W2.y, acc[2][i]);
                    }
                }
            }
            #pragma unroll
            for (int mt = 0; mt < 3; mt++) {
                #pragma unroll
                for (int i = 0; i < 8; i++) {
                    int row = rg*8 + i;
                    if (row < NJ) {
                        float lo, hi; up2(acc[mt][i], lo, hi);
                        qsw[(sd*3+mt)*120 + row*8 + dd] = lo + hi;
                    }
                }
            }
            __syncwarp();
            {
                const int pr = lane >> 4;
                const int n  = lane & 15;
                if (n < NJ) {
                    float sc[NJ];
                    if (pr == 0) {
                        ulonglong2 Q0 = *reinterpret_cast<const ulonglong2*>(qsw + 0*120 + n*8);
                        ulonglong2 Q1 = *reinterpret_cast<const ulonglong2*>(qsw + 0*120 + n*8 + 4);
                        #pragma unroll
                        for (int m = 0; m < NJ; m++) {
                            ulonglong2 K0 = *reinterpret_cast<const ulonglong2*>(qsw + 1*120 + m*8);
                            ulonglong2 K1 = *reinterpret_cast<const ulonglong2*>(qsw + 1*120 + m*8 + 4);
                            u64t t2 = ml2(Q0.x, K0.x);
                            t2 = fm2(Q0.y, K0.y, t2);
                            t2 = fm2(Q1.x, K1.x, t2);
                            t2 = fm2(Q1.y, K1.y, t2);
                            float lo, hi; up2(t2, lo, hi);
                            sc[m] = lo + hi;
                        }
                    } else {
                        ulonglong2 U0 = *reinterpret_cast<const ulonglong2*>(qsw + 3*120 + n*8);
                        ulonglong2 U1 = *reinterpret_cast<const ulonglong2*>(qsw + 3*120 + n*8 + 4);
                        float iv[8];
                        {
                            float4 v0 = *reinterpret_cast<float4*>(qsw + 5*120 + n*8);
                            float4 v1 = *reinterpret_cast<float4*>(qsw + 5*120 + n*8 + 4);
                            iv[0]=v0.x; iv[1]=v0.y; iv[2]=v0.z; iv[3]=v0.w;
                            iv[4]=v1.x; iv[5]=v1.y; iv[6]=v1.z; iv[7]=v1.w;
                        }
                        #pragma unroll
                        for (int m = 0; m < NJ; m++) {
                            ulonglong2 I0 = *reinterpret_cast<const ulonglong2*>(qsw + 4*120 + m*8);
                            ulonglong2 I1 = *reinterpret_cast<const ulonglong2*>(qsw + 4*120 + m*8 + 4);
                            u64t t2 = ml2(U0.x, I0.x);
                            t2 = fm2(U0.y, I0.y, t2);
                            t2 = fm2(U1.x, I1.x, t2);
                            t2 = fm2(U1.y, I1.y, t2);
                            float lo, hi; up2(t2, lo, hi);
                            float t = cbuf[128+m];
                            #pragma unroll
                            for (int d3 = 0; d3 < 8; d3++)
                                t = fmaf(iv[d3], cbuf[d3*16 + m], t);
                            sc[m] = t + lo + hi;
                        }
                    }
                    #pragma unroll
                    for (int m = 0; m < NJ; m++) {
                        float o2 = __shfl_xor_sync(0x7fff7fffu, sc[m], 16);
                        sc[m] = (sc[m] + o2) * 0.6f;
                    }
                    float mx = sc[0];
                    #pragma unroll
                    for (int m = 1; m < NJ; m++) mx = fmaxf(mx, sc[m]);
                    float sum = 0.f;
                    #pragma unroll
                    for (int m = 0; m < NJ; m++) { sc[m] = __expf(sc[m]-mx); sum += sc[m]; }
                    float rs = 1.0f/sum;
                    u64t o0 = 0ull, o1 = 0ull;
                    const float* jvh = qsw + 2*120 + pr*4;
                    #pragma unroll
                    for (int m = 0; m < NJ; m++) {
                        float pm = sc[m]*rs;
                        u64t pm2 = pk2(pm, pm);
                        ulonglong2 Jh = *reinterpret_cast<const ulonglong2*>(jvh + m*8);
                        o0 = fm2(pm2, Jh.x, o0);
                        o1 = fm2(pm2, Jh.y, o1);
                    }
                    *reinterpret_cast<ulonglong2*>(ao + n*132 + h*8 + pr*4) =
                        make_ulonglong2(o0, o1);
                }
            }
        }

        // ---- proj: ping-pong staging, 1 sync per chunk (+1 entry) ----
        #pragma unroll
        for (int i = 0; i < 11; i++) {
            int idx = tid + i*384;
            if (idx < 4096) st[i] = Pw[idx];
        }
        __syncthreads();   // attention wbuf readers done
        u64t xa[8], xb[8];
        #pragma unroll
        for (int i = 0; i < 8; i++) { xa[i]=pk2(x[i][0],x[i][1]); xb[i]=pk2(x[i][2],x[i][3]); }
        #pragma unroll 1
        for (int kc = 0; kc < 4; kc++) {
            float* bp = wbuf + (kc&1)*4096;
            #pragma unroll
            for (int i = 0; i < 11; i++) {
                int idx = tid + i*384;
                if (idx < 4096) bp[idx] = st[i];
            }
            __syncthreads();
            if (kc < 3) {
                #pragma unroll
                for (int i = 0; i < 11; i++) {
                    int idx = tid + i*384;
                    if (idx < 4096) st[i] = Pw[(kc+1)*4096 + idx];
                }
            }
            #pragma unroll 1
            for (int kk4 = 0; kk4 < 8; kk4++) {
                float a4[8][4];
                #pragma unroll
                for (int i = 0; i < 8; i++) {
                    int row = r0+i; row = row < NJ ? row : (NJ-1);
                    float4 t = *reinterpret_cast<float4*>(ao + row*132 + kc*32 + kk4*4);
                    a4[i][0]=t.x; a4[i][1]=t.y; a4[i][2]=t.z; a4[i][3]=t.w;
                }
                #pragma unroll
                for (int j = 0; j < 4; j++) {
                    ulonglong2 Wv = *reinterpret_cast<const ulonglong2*>(bp + (kk4*4+j)*128 + c0);
                    #pragma unroll
                    for (int i = 0; i < 8; i++) {
                        u64t ad = pk2(a4[i][j], a4[i][j]);
                        xa[i] = fm2(ad, Wv.x, xa[i]);
                        xb[i] = fm2(ad, Wv.y, xb[i]);
                    }
                }
            }
        }
        #pragma unroll
        for (int i = 0; i < 8; i++) { up2(xa[i],x[i][0],x[i][1]); up2(xb[i],x[i][2],x[i][3]); }
        {
            float4 pb = *reinterpret_cast<const float4*>(proj_b + L*128 + c0);
            #pragma unroll
            for (int i = 0; i < 8; i++) {
                x[i][0]+=pb.x; x[i][1]+=pb.y; x[i][2]+=pb.z; x[i][3]+=pb.w;
            }
        }
        {
            float4 w3 = *reinterpret_cast<const float4*>(ln3_w + L*128 + c0);
            float4 b3 = *reinterpret_cast<const float4*>(ln3_b + L*128 + c0);
            #pragma unroll
            for (int i = 0; i < 8; i++) {
                float mu, inv;
                row_stats4(x[i][0], x[i][1], x[i][2], x[i][3], mu, inv);
                int row = r0+i;
                if (row < NJ) {
                    float4 o;
                    o.x = fmaf((x[i][0]-mu)*inv, w3.x, b3.x);
                    o.y = fmaf((x[i][1]-mu)*inv, w3.y, b3.y);
                    o.z = fmaf((x[i][2]-mu)*inv, w3.z, b3.z);
                    o.w = fmaf((x[i][3]-mu)*inv, w3.w, b3.w);
                    *reinterpret_cast<float4*>(jn + RO(row) + c0) = o;
                }
            }
        }
        // ---- fc1 ----
        u64t ha2[8];
        {
            float2 fb = *reinterpret_cast<const float2*>(fc1_b + L*64 + lane*2);
            #pragma unroll
            for (int i = 0; i < 8; i++) ha2[i] = pk2(fb.x, fb.y);
        }
        #pragma unroll
        for (int i = 0; i < 11; i++) {
            int idx = tid + i*384;
            if (idx < 4096) st[i] = fc1_w[L*8192 + idx];
        }
        #pragma unroll 1
        for (int kc = 0; kc < 2; kc++) {
            float* bp = wbuf + (kc&1)*4096;
            #pragma unroll
            for (int i = 0; i < 11; i++) {
                int idx = tid + i*384;
                if (idx < 4096) bp[idx] = st[i];
            }
            __syncthreads();
            if (kc < 1) {
                #pragma unroll
                for (int i = 0; i < 11; i++) {
                    int idx = tid + i*384;
                    if (idx < 4096) st[i] = fc1_w[L*8192 + 4096 + idx];
                }
            }
            #pragma unroll 1
            for (int kk4 = 0; kk4 < 16; kk4++) {
                float a4[8][4];
                #pragma unroll
                for (int i = 0; i < 8; i++) {
                    int row = r0+i; row = row < NJ ? row : (NJ-1);
                    float4 t = *reinterpret_cast<float4*>(jn + RO(row) + kc*64 + kk4*4);
                    a4[i][0]=t.x; a4[i][1]=t.y; a4[i][2]=t.z; a4[i][3]=t.w;
                }
                #pragma unroll
                for (int j = 0; j < 4; j++) {
                    u64t wv = *reinterpret_cast<const u64t*>(bp + (kk4*4+j)*64 + lane*2);
                    #pragma unroll
                    for (int i = 0; i < 8; i++) {
                        u64t ad = pk2(a4[i][j], a4[i][j]);
                        ha2[i] = fm2(ad, wv, ha2[i]);
                    }
                }
            }
        }
        #pragma unroll
        for (int i = 0; i < 8; i++) {
            int row = r0+i;
            if (row < NJ) {
                float h0, h1; up2(ha2[i], h0, h1);
                float g0 = 0.5f*h0*(1.0f + erff(h0*0.70710678118654752f));
                float g1 = 0.5f*h1*(1.0f + erff(h1*0.70710678118654752f));
                *reinterpret_cast<float2*>(ao + row*64 + lane*2) = make_float2(g0, g1);
            }
        }
        __syncwarp();
        // ---- fc2 ----
        #pragma unroll
        for (int i = 0; i < 11; i++) {
            int idx = tid + i*384;
            if (idx < 4096) st[i] = fc2_w[L*8192 + idx];
        }
        #pragma unroll
        for (int i = 0; i < 8; i++) { xa[i]=pk2(x[i][0],x[i][1]); xb[i]=pk2(x[i][2],x[i][3]); }
        #pragma unroll 1
        for (int kc = 0; kc < 2; kc++) {
            float* bp = wbuf + (kc&1)*4096;
            #pragma unroll
            for (int i = 0; i < 11; i++) {
                int idx = tid + i*384;
                if (idx < 4096) bp[idx] = st[i];
            }
            __syncthreads();
            if (kc < 1) {
                #pragma unroll
                for (int i = 0; i < 11; i++) {
                    int idx = tid + i*384;
                    if (idx < 4096) st[i] = fc2_w[L*8192 + 4096 + idx];
                }
            }
            #pragma unroll 1
            for (int kk4 = 0; kk4 < 8; kk4++) {
                float a4[8][4];
                #pragma unroll
                for (int i = 0; i < 8; i++) {
                    int row = r0+i; row = row < NJ ? row : (NJ-1);
                    float4 t = *reinterpret_cast<float4*>(ao + row*64 + kc*32 + kk4*4);
                    a4[i][0]=t.x; a4[i][1]=t.y; a4[i][2]=t.z; a4[i][3]=t.w;
                }
                #pragma unroll
                for (int j = 0; j < 4; j++) {
                    ulonglong2 Wv = *reinterpret_cast<const ulonglong2*>(bp + (kk4*4+j)*128 + c0);
                    #pragma unroll
                    for (int i = 0; i < 8; i++) {
                        u64t ad = pk2(a4[i][j], a4[i][j]);
                        xa[i] = fm2(ad, Wv.x, xa[i]);
                        xb[i] = fm2(ad, Wv.y, xb[i]);
                    }
                }
            }
        }
        #pragma unroll
        for (int i = 0; i < 8; i++) { up2(xa[i],x[i][0],x[i][1]); up2(xb[i],x[i][2],x[i][3]); }
        {
            float4 fb = *reinterpret_cast<const float4*>(fc2_b + L*128 + c0);
            #pragma unroll
            for (int i = 0; i < 8; i++) {
                x[i][0]+=fb.x; x[i][1]+=fb.y; x[i][2]+=fb.z; x[i][3]+=fb.w;
            }
        }
    }

    if (eb < NB) {
        #pragma unroll
        for (int i = 0; i < 8; i++) {
            int row = r0+i;
            if (row < NJ)
                *reinterpret_cast<float4*>(out + base + row*128 + c0) =
                    make_float4(x[i][0], x[i][1], x[i][2], x[i][3]);
        }
    }
}

extern "C" void kernel_launch(void* const* d_in, const int* in_sizes, int n_in,
                              void* d_out, int out_size) {
    (void)in_sizes; (void)n_in; (void)out_size;
    const float** p = (const float**)d_in;
    bfold_prep<<<NDEPTH, 384>>>(p[5], p[4], p[13]);
    cudaFuncSetAttribute(jr_kernel, cudaFuncAttributeMaxDynamicSharedMemorySize,
                         SMEM_BYTES);
    jr_kernel<<<(NB + EPC - 1)/EPC, NTHR, SMEM_BYTES>>>(
        p[0], p[1], p[2], p[3], p[4], p[5], p[6], p[7], p[8], p[9],
        p[10], p[11], p[12], p[13], p[14], p[15], p[16], p[17], p[18], p[19],
        (float*)d_out);
}

// round 15
// speedup vs baseline: 1.7483x; 1.0494x over previous
#include <cuda_runtime.h>
#define NB 16384
#define NJ 15
#define NDEPTH 6
#define EPC 6
#define NTHR 384
#define RO(r) ((r)*128 + (((r)>>3)<<3))
#define RNOFF 2064
#define AOOFF 4128
#define QSOFF 6112
#define ESTRIDE 7552
#define WBUF_OFF (EPC*ESTRIDE)
#define CBUF_OFF (WBUF_OFF+8192)
#define LN2C_OFF (CBUF_OFF+144)
#define BFOLD_OFF (LN2C_OFF+128)
#define SMEM_FLOATS (BFOLD_OFF+384)
#define SMEM_BYTES (SMEM_FLOATS*4)

__device__ float g_bfold[NDEPTH*384];

typedef unsigned long long u64t;
__device__ __forceinline__ u64t pk2(float lo, float hi) {
    u64t r; asm("mov.b64 %0, {%1,%2};" : "=l"(r) : "f"(lo), "f"(hi)); return r;
}
__device__ __forceinline__ void up2(u64t p, float& lo, float& hi) {
    asm("mov.b64 {%0,%1}, %2;" : "=f"(lo), "=f"(hi) : "l"(p));
}
__device__ __forceinline__ u64t fm2(u64t a, u64t b, u64t c) {
    u64t d; asm("fma.rn.f32x2 %0, %1, %2, %3;" : "=l"(d) : "l"(a), "l"(b), "l"(c)); return d;
}
__device__ __forceinline__ u64t ml2(u64t a, u64t b) {
    u64t d; asm("mul.rn.f32x2 %0, %1, %2;" : "=l"(d) : "l"(a), "l"(b)); return d;
}
__device__ __forceinline__ void row_stats4(float v0, float v1, float v2, float v3,
                                           float& mu, float& inv) {
    float s = v0+v1+v2+v3, ss = v0*v0+v1*v1+v2*v2+v3*v3;
    #pragma unroll
    for (int off = 16; off > 0; off >>= 1) {
        s  += __shfl_xor_sync(0xffffffffu, s,  off);
        ss += __shfl_xor_sync(0xffffffffu, ss, off);
    }
    mu = s * (1.0f/128.0f);
    inv = rsqrtf(ss * (1.0f/128.0f) - mu*mu + 1e-5f);
}

__global__ void bfold_prep(const float* __restrict__ Iqk_b,
                           const float* __restrict__ Iqk_w,
                           const float* __restrict__ ln2_b) {
    int L = blockIdx.x, c = threadIdx.x;
    float a = Iqk_b[L*384 + c];
    const float* wc = Iqk_w + L*49152 + c;
    const float* b2 = ln2_b + L*128;
    #pragma unroll 8
    for (int k = 0; k < 128; k++)
        a = fmaf(__ldg(b2+k), __ldg(wc + k*384), a);
    g_bfold[L*384 + c] = a;
}

__global__ __launch_bounds__(NTHR, 1)
void jr_kernel(const float* __restrict__ joint, const float* __restrict__ rel,
               const float* __restrict__ Jqkv_w, const float* __restrict__ Jqkv_b,
               const float* __restrict__ Iqk_w,  const float* __restrict__ Iqk_b,
               const float* __restrict__ Iconv_w,const float* __restrict__ Iconv_b,
               const float* __restrict__ proj_w, const float* __restrict__ proj_b,
               const float* __restrict__ ln1_w,  const float* __restrict__ ln1_b,
               const float* __restrict__ ln2_w,  const float* __restrict__ ln2_b,
               const float* __restrict__ ln3_w,  const float* __restrict__ ln3_b,
               const float* __restrict__ fc1_w,  const float* __restrict__ fc1_b,
               const float* __restrict__ fc2_w,  const float* __restrict__ fc2_b,
               float* __restrict__ out)
{
    extern __shared__ float sm[];
    const int tid = threadIdx.x, wid = tid>>5;
    // SMSP-spread group mapping: group ws = wid/6; both groups on every SMSP
    const int ws   = wid >= 6;
    const int elem = ws ? (wid - 6) : wid;
    const int lane = tid&31, c0 = lane*4, r0 = ws*8;
    const int rg = lane>>4, cg = lane&15, sd = cg>>3, dd = cg&7;
    const int tg  = elem*32 + lane;
    const int col = tg % 48;
    const int kk0 = tg / 48;
    const int sI  = col >= 24;
    const int c2  = col - sI*24;
    const int gcb0 = (c2>>3)*128 + ws*8 + (c2&7);
    const int ssm0 = ws*3456 + col*36 + kk0;

    float* jn  = sm + elem*ESTRIDE;
    float* rn  = jn + RNOFF;
    float* ao  = jn + AOOFF;
    float* qsw = jn + QSOFF + ws*720;
    float* wbuf  = sm + WBUF_OFF;
    float* cbuf  = sm + CBUF_OFF;
    float* ln2c  = sm + LN2C_OFF;
    float* bfold = sm + BFOLD_OFF;

    const int eb = blockIdx.x*EPC + elem;
    const int e  = eb < NB ? eb : (NB-1);
    const long base = (long)e * (NJ*128);
    float st[11];

    float x[8][4];
    #pragma unroll
    for (int i = 0; i < 8; i++) {
        int row = r0+i, grow = row < NJ ? row : (NJ-1);
        float4 v = *reinterpret_cast<const float4*>(joint + base + grow*128 + c0);
        x[i][0]=v.x; x[i][1]=v.y; x[i][2]=v.z; x[i][3]=v.w;
    }
    #pragma unroll
    for (int i = 0; i < 8; i++) {
        int row = r0+i, grow = row < NJ ? row : (NJ-1);
        float4 v = *reinterpret_cast<const float4*>(rel + base + grow*128 + c0);
        float mu, inv;
        row_stats4(v.x, v.y, v.z, v.w, mu, inv);
        if (row < NJ) {
            float4 o;
            o.x=(v.x-mu)*inv; o.y=(v.y-mu)*inv; o.z=(v.z-mu)*inv; o.w=(v.w-mu)*inv;
            *reinterpret_cast<float4*>(rn + RO(row) + c0) = o;
        }
    }
    {
        float4 z = make_float4(0.f,0.f,0.f,0.f);
        *reinterpret_cast<float4*>(jn + RO(15) + c0) = z;
        *reinterpret_cast<float4*>(rn + RO(15) + c0) = z;
    }

    #pragma unroll 1
    for (int L = 0; L < NDEPTH; L++) {
        const float* Jw = Jqkv_w + L*49152;
        const float* Jb = Jqkv_b + L*384;
        const float* Iw = Iqk_w  + L*49152;
        const float* Pw = proj_w + L*16384;
        const float* Sw = sI ? Iw : Jw;

        __syncthreads();
        if (tid < 128) {
            int d2 = tid>>4, m = tid&15;
            cbuf[tid] = (m < NJ) ? Iconv_w[L*(8*NJ) + d2*NJ + m] : 0.f;
            ln2c[tid] = ln2_w[L*128 + tid];
        } else if (tid < 144) {
            int m = tid-128;
            cbuf[128+m] = (m < NJ) ? Iconv_b[L*NJ + m] : 0.f;
        }
        if (tid < 384) bfold[tid] = g_bfold[L*384 + tid];
        {
            float4 w1 = *reinterpret_cast<const float4*>(ln1_w + L*128 + c0);
            float4 b1 = *reinterpret_cast<const float4*>(ln1_b + L*128 + c0);
            #pragma unroll
            for (int i = 0; i < 8; i++) {
                float mu, inv;
                row_stats4(x[i][0], x[i][1], x[i][2], x[i][3], mu, inv);
                int row = r0+i;
                if (row < NJ) {
                    float4 o;
                    o.x = fmaf((x[i][0]-mu)*inv, w1.x, b1.x);
                    o.y = fmaf((x[i][1]-mu)*inv, w1.y, b1.y);
                    o.z = fmaf((x[i][2]-mu)*inv, w1.z, b1.z);
                    o.w = fmaf((x[i][3]-mu)*inv, w1.w, b1.w);
                    *reinterpret_cast<float4*>(jn + RO(row) + c0) = o;
                }
            }
        }
        __syncthreads();

        // prefetch attention chunk (r=0,q=0)
        {
            const float* gp = Sw + gcb0 + kk0*384;
            const float* lp = ln2c + kk0;
            #pragma unroll
            for (int i = 0; i < 8; i++)
                st[i] = sI ? gp[i*1536]*lp[4*i] : gp[i*1536];
        }
        #pragma unroll 1
        for (int r = 0; r < 8; r++) {
            const int h = r*2 + ws;
            u64t acc[3][8];
            #pragma unroll
            for (int mt = 0; mt < 3; mt++) {
                float bv = sd ? bfold[mt*128 + h*8 + dd] : __ldg(Jb + mt*128 + h*8 + dd);
                #pragma unroll
                for (int i = 0; i < 8; i++) acc[mt][i] = pk2(bv, 0.f);
            }
            #pragma unroll 1
            for (int q = 0; q < 4; q++) {
                const int p = q & 1;
                #pragma unroll
                for (int i = 0; i < 8; i++) wbuf[ssm0 + p*1728 + 4*i] = st[i];
                asm volatile("bar.sync %0, %1;" :: "r"(2+ws), "r"(192) : "memory");
                {
                    int nr = r, nq = q + 1;
                    if (nq == 4) { nq = 0; nr++; }
                    if (nr < 8) {
                        const float* gp = Sw + gcb0 + nr*16 + (nq*32 + kk0)*384;
                        const float* lp = ln2c + nq*32 + kk0;
                        #pragma unroll
                        for (int i = 0; i < 8; i++)
                            st[i] = sI ? gp[i*1536]*lp[4*i] : gp[i*1536];
                    }
                }
                const float* ap  = jn + sd*RNOFF + rg*1032 + q*32;
                const float* w0p = wbuf + ws*3456 + p*1728 + (sd*24 + dd)*36;
                const float* w1p = w0p + 288;
                const float* w2p = w0p + 576;
                #pragma unroll 4
                for (int k = 0; k < 32; k += 4) {
                    ulonglong2 W0 = *reinterpret_cast<const ulonglong2*>(w0p + k);
                    ulonglong2 W1 = *reinterpret_cast<const ulonglong2*>(w1p + k);
                    ulonglong2 W2 = *reinterpret_cast<const ulonglong2*>(w2p + k);
                    #pragma unroll
                    for (int i = 0; i < 8; i++) {
                        ulonglong2 A = *reinterpret_cast<const ulonglong2*>(ap + i*128 + k);
                        acc[0][i] = fm2(A.x, W0.x, acc[0][i]);
                        acc[0][i] = fm2(A.y, W0.y, acc[0][i]);
                        acc[1][i] = fm2(A.x, W1.x, acc[1][i]);
                        acc[1][i] = fm2(A.y, W1.y, acc[1][i]);
                        acc[2][i] = fm2(A.x, W2.x, acc[2][i]);
                        acc[2][i] = fm2(A.y, W2.y, acc[2][i]);
                    }
                }
            }
            #pragma unroll
            for (int mt = 0; mt < 3; mt++) {
                #pragma unroll
                for (int i = 0; i < 8; i++) {
                    int row = rg*8 + i;
                    if (row < NJ) {
                        float lo, hi; up2(acc[mt][i], lo, hi);
                        qsw[(sd*3+mt)*120 + row*8 + dd] = lo + hi;
                    }
                }
            }
            __syncwarp();
            {
                const int pr = lane >> 4;
                const int n  = lane & 15;
                if (n < NJ) {
                    float sc[NJ];
                    if (pr == 0) {
                        ulonglong2 Q0 = *reinterpret_cast<const ulonglong2*>(qsw + 0*120 + n*8);
                        ulonglong2 Q1 = *reinterpret_cast<const ulonglong2*>(qsw + 0*120 + n*8 + 4);
                        #pragma unroll
                        for (int m = 0; m < NJ; m++) {
                            ulonglong2 K0 = *reinterpret_cast<const ulonglong2*>(qsw + 1*120 + m*8);
                            ulonglong2 K1 = *reinterpret_cast<const ulonglong2*>(qsw + 1*120 + m*8 + 4);
                            u64t t2 = ml2(Q0.x, K0.x);
                            t2 = fm2(Q0.y, K0.y, t2);
                            t2 = fm2(Q1.x, K1.x, t2);
                            t2 = fm2(Q1.y, K1.y, t2);
                            float lo, hi; up2(t2, lo, hi);
                            sc[m] = lo + hi;
                        }
                    } else {
                        ulonglong2 U0 = *reinterpret_cast<const ulonglong2*>(qsw + 3*120 + n*8);
                        ulonglong2 U1 = *reinterpret_cast<const ulonglong2*>(qsw + 3*120 + n*8 + 4);
                        float iv[8];
                        {
                            float4 v0 = *reinterpret_cast<float4*>(qsw + 5*120 + n*8);
                            float4 v1 = *reinterpret_cast<float4*>(qsw + 5*120 + n*8 + 4);
                            iv[0]=v0.x; iv[1]=v0.y; iv[2]=v0.z; iv[3]=v0.w;
                            iv[4]=v1.x; iv[5]=v1.y; iv[6]=v1.z; iv[7]=v1.w;
                        }
                        #pragma unroll
                        for (int m = 0; m < NJ; m++) {
                            ulonglong2 I0 = *reinterpret_cast<const ulonglong2*>(qsw + 4*120 + m*8);
                            ulonglong2 I1 = *reinterpret_cast<const ulonglong2*>(qsw + 4*120 + m*8 + 4);
                            u64t t2 = ml2(U0.x, I0.x);
                            t2 = fm2(U0.y, I0.y, t2);
                            t2 = fm2(U1.x, I1.x, t2);
                            t2 = fm2(U1.y, I1.y, t2);
                            float lo, hi; up2(t2, lo, hi);
                            float t = cbuf[128+m];
                            #pragma unroll
                            for (int d3 = 0; d3 < 8; d3++)
                                t = fmaf(iv[d3], cbuf[d3*16 + m], t);
                            sc[m] = t + lo + hi;
                        }
                    }
                    #pragma unroll
                    for (int m = 0; m < NJ; m++) {
                        float o2 = __shfl_xor_sync(0x7fff7fffu, sc[m], 16);
                        sc[m] = (sc[m] + o2) * 0.6f;
                    }
                    float mx = sc[0];
                    #pragma unroll
                    for (int m = 1; m < NJ; m++) mx = fmaxf(mx, sc[m]);
                    float sum = 0.f;
                    #pragma unroll
                    for (int m = 0; m < NJ; m++) { sc[m] = __expf(sc[m]-mx); sum += sc[m]; }
                    float rs = 1.0f/sum;
                    u64t o0 = 0ull, o1 = 0ull;
                    const float* jvh = qsw + 2*120 + pr*4;
                    #pragma unroll
                    for (int m = 0; m < NJ; m++) {
                        float pm = sc[m]*rs;
                        u64t pm2 = pk2(pm, pm);
                        ulonglong2 Jh = *reinterpret_cast<const ulonglong2*>(jvh + m*8);
                        o0 = fm2(pm2, Jh.x, o0);
                        o1 = fm2(pm2, Jh.y, o1);
                    }
                    *reinterpret_cast<ulonglong2*>(ao + n*132 + h*8 + pr*4) =
                        make_ulonglong2(o0, o1);
                }
            }
        }

        // ---- proj: ping-pong staging ----
        #pragma unroll
        for (int i = 0; i < 11; i++) {
            int idx = tid + i*384;
            if (idx < 4096) st[i] = Pw[idx];
        }
        __syncthreads();
        u64t xa[8], xb[8];
        #pragma unroll
        for (int i = 0; i < 8; i++) { xa[i]=pk2(x[i][0],x[i][1]); xb[i]=pk2(x[i][2],x[i][3]); }
        #pragma unroll 1
        for (int kc = 0; kc < 4; kc++) {
            float* bp = wbuf + (kc&1)*4096;
            #pragma unroll
            for (int i = 0; i < 11; i++) {
                int idx = tid + i*384;
                if (idx < 4096) bp[idx] = st[i];
            }
            __syncthreads();
            if (kc < 3) {
                #pragma unroll
                for (int i = 0; i < 11; i++) {
                    int idx = tid + i*384;
                    if (idx < 4096) st[i] = Pw[(kc+1)*4096 + idx];
                }
            }
            #pragma unroll 1
            for (int kk4 = 0; kk4 < 8; kk4++) {
                float a4[8][4];
                #pragma unroll
                for (int i = 0; i < 8; i++) {
                    int row = r0+i; row = row < NJ ? row : (NJ-1);
                    float4 t = *reinterpret_cast<float4*>(ao + row*132 + kc*32 + kk4*4);
                    a4[i][0]=t.x; a4[i][1]=t.y; a4[i][2]=t.z; a4[i][3]=t.w;
                }
                #pragma unroll
                for (int j = 0; j < 4; j++) {
                    ulonglong2 Wv = *reinterpret_cast<const ulonglong2*>(bp + (kk4*4+j)*128 + c0);
                    #pragma unroll
                    for (int i = 0; i < 8; i++) {
                        u64t ad = pk2(a4[i][j], a4[i][j]);
                        xa[i] = fm2(ad, Wv.x, xa[i]);
                        xb[i] = fm2(ad, Wv.y, xb[i]);
                    }
                }
            }
        }
        #pragma unroll
        for (int i = 0; i < 8; i++) { up2(xa[i],x[i][0],x[i][1]); up2(xb[i],x[i][2],x[i][3]); }
        {
            float4 pb = *reinterpret_cast<const float4*>(proj_b + L*128 + c0);
            #pragma unroll
            for (int i = 0; i < 8; i++) {
                x[i][0]+=pb.x; x[i][1]+=pb.y; x[i][2]+=pb.z; x[i][3]+=pb.w;
            }
        }
        {
            float4 w3 = *reinterpret_cast<const float4*>(ln3_w + L*128 + c0);
            float4 b3 = *reinterpret_cast<const float4*>(ln3_b + L*128 + c0);
            #pragma unroll
            for (int i = 0; i < 8; i++) {
                float mu, inv;
                row_stats4(x[i][0], x[i][1], x[i][2], x[i][3], mu, inv);
                int row = r0+i;
                if (row < NJ) {
                    float4 o;
                    o.x = fmaf((x[i][0]-mu)*inv, w3.x, b3.x);
                    o.y = fmaf((x[i][1]-mu)*inv, w3.y, b3.y);
                    o.z = fmaf((x[i][2]-mu)*inv, w3.z, b3.z);
                    o.w = fmaf((x[i][3]-mu)*inv, w3.w, b3.w);
                    *reinterpret_cast<float4*>(jn + RO(row) + c0) = o;
                }
            }
        }
        // ---- fc1 ----
        u64t ha2[8];
        {
            float2 fb = *reinterpret_cast<const float2*>(fc1_b + L*64 + lane*2);
            #pragma unroll
            for (int i = 0; i < 8; i++) ha2[i] = pk2(fb.x, fb.y);
        }
        #pragma unroll
        for (int i = 0; i < 11; i++) {
            int idx = tid + i*384;
            if (idx < 4096) st[i] = fc1_w[L*8192 + idx];
        }
        #pragma unroll 1
        for (int kc = 0; kc < 2; kc++) {
            float* bp = wbuf + (kc&1)*4096;
            #pragma unroll
            for (int i = 0; i < 11; i++) {
                int idx = tid + i*384;
                if (idx < 4096) bp[idx] = st[i];
            }
            __syncthreads();
            if (kc < 1) {
                #pragma unroll
                for (int i = 0; i < 11; i++) {
                    int idx = tid + i*384;
                    if (idx < 4096) st[i] = fc1_w[L*8192 + 4096 + idx];
                }
            }
            #pragma unroll 1
            for (int kk4 = 0; kk4 < 16; kk4++) {
                float a4[8][4];
                #pragma unroll
                for (int i = 0; i < 8; i++) {
                    int row = r0+i; row = row < NJ ? row : (NJ-1);
                    float4 t = *reinterpret_cast<float4*>(jn + RO(row) + kc*64 + kk4*4);
                    a4[i][0]=t.x; a4[i][1]=t.y; a4[i][2]=t.z; a4[i][3]=t.w;
                }
                #pragma unroll
                for (int j = 0; j < 4; j++) {
                    u64t wv = *reinterpret_cast<const u64t*>(bp + (kk4*4+j)*64 + lane*2);
                    #pragma unroll
                    for (int i = 0; i < 8; i++) {
                        u64t ad = pk2(a4[i][j], a4[i][j]);
                        ha2[i] = fm2(ad, wv, ha2[i]);
                    }
                }
            }
        }
        #pragma unroll
        for (int i = 0; i < 8; i++) {
            int row = r0+i;
            if (row < NJ) {
                float h0, h1; up2(ha2[i], h0, h1);
                float g0 = 0.5f*h0*(1.0f + erff(h0*0.70710678118654752f));
                float g1 = 0.5f*h1*(1.0f + erff(h1*0.70710678118654752f));
                *reinterpret_cast<float2*>(ao + row*64 + lane*2) = make_float2(g0, g1);
            }
        }
        __syncwarp();
        // ---- fc2 ----
        #pragma unroll
        for (int i = 0; i < 11; i++) {
            int idx = tid + i*384;
            if (idx < 4096) st[i] = fc2_w[L*8192 + idx];
        }
        #pragma unroll
        for (int i = 0; i < 8; i++) { xa[i]=pk2(x[i][0],x[i][1]); xb[i]=pk2(x[i][2],x[i][3]); }
        #pragma unroll 1
        for (int kc = 0; kc < 2; kc++) {
            float* bp = wbuf + (kc&1)*4096;
            #pragma unroll
            for (int i = 0; i < 11; i++) {
                int idx = tid + i*384;
                if (idx < 4096) bp[idx] = st[i];
            }
            __syncthreads();
            if (kc < 1) {
                #pragma unroll
                for (int i = 0; i < 11; i++) {
                    int idx = tid + i*384;
                    if (idx < 4096) st[i] = fc2_w[L*8192 + 4096 + idx];
                }
            }
            #pragma unroll 1
            for (int kk4 = 0; kk4 < 8; kk4++) {
                float a4[8][4];
                #pragma unroll
                for (int i = 0; i < 8; i++) {
                    int row = r0+i; row = row < NJ ? row : (NJ-1);
                    float4 t = *reinterpret_cast<float4*>(ao + row*64 + kc*32 + kk4*4);
                    a4[i][0]=t.x; a4[i][1]=t.y; a4[i][2]=t.z; a4[i][3]=t.w;
                }
                #pragma unroll
                for (int j = 0; j < 4; j++) {
                    ulonglong2 Wv = *reinterpret_cast<const ulonglong2*>(bp + (kk4*4+j)*128 + c0);
                    #pragma unroll
                    for (int i = 0; i < 8; i++) {
                        u64t ad = pk2(a4[i][j], a4[i][j]);
                        xa[i] = fm2(ad, Wv.x, xa[i]);
                        xb[i] = fm2(ad, Wv.y, xb[i]);
                    }
                }
            }
        }
        #pragma unroll
        for (int i = 0; i < 8; i++) { up2(xa[i],x[i][0],x[i][1]); up2(xb[i],x[i][2],x[i][3]); }
        {
            float4 fb = *reinterpret_cast<const float4*>(fc2_b + L*128 + c0);
            #pragma unroll
            for (int i = 0; i < 8; i++) {
                x[i][0]+=fb.x; x[i][1]+=fb.y; x[i][2]+=fb.z; x[i][3]+=fb.w;
            }
        }
    }

    if (eb < NB) {
        #pragma unroll
        for (int i = 0; i < 8; i++) {
            int row = r0+i;
            if (row < NJ)
                *reinterpret_cast<float4*>(out + base + row*128 + c0) =
                    make_float4(x[i][0], x[i][1], x[i][2], x[i][3]);
        }
    }
}

extern "C" void kernel_launch(void* const* d_in, const int* in_sizes, int n_in,
                              void* d_out, int out_size) {
    (void)in_sizes; (void)n_in; (void)out_size;
    const float** p = (const float**)d_in;
    bfold_prep<<<NDEPTH, 384>>>(p[5], p[4], p[13]);
    cudaFuncSetAttribute(jr_kernel, cudaFuncAttributeMaxDynamicSharedMemorySize,
                         SMEM_BYTES);
    jr_kernel<<<(NB + EPC - 1)/EPC, NTHR, SMEM_BYTES>>>(
        p[0], p[1], p[2], p[3], p[4], p[5], p[6], p[7], p[8], p[9],
        p[10], p[11], p[12], p[13], p[14], p[15], p[16], p[17], p[18], p[19],
        (float*)d_out);
}

// round 16
// speedup vs baseline: 1.7859x; 1.0215x over previous
#include <cuda_runtime.h>
#define NB 16384
#define NJ 15
#define NDEPTH 6
#define EPC 6
#define NTHR 384
#define RO(r) ((r)*128 + (((r)>>3)<<3))
#define RNOFF 2064
#define AOOFF 4128
#define QSOFF 6112
#define ESTRIDE 7552
#define WBUF_OFF (EPC*ESTRIDE)
#define JB_OFF   (WBUF_OFF+8192)
#define CBUF_OFF (JB_OFF+384)
#define LN2C_OFF (CBUF_OFF+144)
#define BFOLD_OFF (LN2C_OFF+128)
#define SMEM_FLOATS (BFOLD_OFF+384)
#define SMEM_BYTES (SMEM_FLOATS*4)

__device__ float g_bfold[NDEPTH*384];

typedef unsigned long long u64t;
__device__ __forceinline__ u64t pk2(float lo, float hi) {
    u64t r; asm("mov.b64 %0, {%1,%2};" : "=l"(r) : "f"(lo), "f"(hi)); return r;
}
__device__ __forceinline__ void up2(u64t p, float& lo, float& hi) {
    asm("mov.b64 {%0,%1}, %2;" : "=f"(lo), "=f"(hi) : "l"(p));
}
__device__ __forceinline__ u64t fm2(u64t a, u64t b, u64t c) {
    u64t d; asm("fma.rn.f32x2 %0, %1, %2, %3;" : "=l"(d) : "l"(a), "l"(b), "l"(c)); return d;
}
__device__ __forceinline__ u64t ml2(u64t a, u64t b) {
    u64t d; asm("mul.rn.f32x2 %0, %1, %2;" : "=l"(d) : "l"(a), "l"(b)); return d;
}
__device__ __forceinline__ void row_stats4(float v0, float v1, float v2, float v3,
                                           float& mu, float& inv) {
    float s = v0+v1+v2+v3, ss = v0*v0+v1*v1+v2*v2+v3*v3;
    #pragma unroll
    for (int off = 16; off > 0; off >>= 1) {
        s  += __shfl_xor_sync(0xffffffffu, s,  off);
        ss += __shfl_xor_sync(0xffffffffu, ss, off);
    }
    mu = s * (1.0f/128.0f);
    inv = rsqrtf(ss * (1.0f/128.0f) - mu*mu + 1e-5f);
}

__global__ void bfold_prep(const float* __restrict__ Iqk_b,
                           const float* __restrict__ Iqk_w,
                           const float* __restrict__ ln2_b) {
    int L = blockIdx.x, c = threadIdx.x;
    float a = Iqk_b[L*384 + c];
    const float* wc = Iqk_w + L*49152 + c;
    const float* b2 = ln2_b + L*128;
    #pragma unroll 8
    for (int k = 0; k < 128; k++)
        a = fmaf(__ldg(b2+k), __ldg(wc + k*384), a);
    g_bfold[L*384 + c] = a;
}

__global__ __launch_bounds__(NTHR, 1)
void jr_kernel(const float* __restrict__ joint, const float* __restrict__ rel,
               const float* __restrict__ Jqkv_w, const float* __restrict__ Jqkv_b,
               const float* __restrict__ Iqk_w,  const float* __restrict__ Iqk_b,
               const float* __restrict__ Iconv_w,const float* __restrict__ Iconv_b,
               const float* __restrict__ proj_w, const float* __restrict__ proj_b,
               const float* __restrict__ ln1_w,  const float* __restrict__ ln1_b,
               const float* __restrict__ ln2_w,  const float* __restrict__ ln2_b,
               const float* __restrict__ ln3_w,  const float* __restrict__ ln3_b,
               const float* __restrict__ fc1_w,  const float* __restrict__ fc1_b,
               const float* __restrict__ fc2_w,  const float* __restrict__ fc2_b,
               float* __restrict__ out)
{
    extern __shared__ float sm[];
    const int tid = threadIdx.x, wid = tid>>5;
    const int ws   = wid >= 6;
    const int elem = ws ? (wid - 6) : wid;
    const int lane = tid&31, c0 = lane*4, r0 = ws*8;
    const int rg = lane>>4, cg = lane&15, sd = cg>>3, dd = cg&7;
    const int tg  = elem*32 + lane;
    const int col = tg % 48;
    const int kk0 = tg / 48;
    const int sI  = col >= 24;
    const int c2  = col - sI*24;
    const int gcb0 = (c2>>3)*128 + ws*8 + (c2&7);
    const int ssm0 = ws*3456 + col*36 + kk0;

    float* jn  = sm + elem*ESTRIDE;
    float* rn  = jn + RNOFF;
    float* ao  = jn + AOOFF;
    float* qsw = jn + QSOFF + ws*720;
    float* wbuf  = sm + WBUF_OFF;
    float* jbsm  = sm + JB_OFF;
    float* cbuf  = sm + CBUF_OFF;
    float* ln2c  = sm + LN2C_OFF;
    float* bfold = sm + BFOLD_OFF;

    const int eb = blockIdx.x*EPC + elem;
    const int e  = eb < NB ? eb : (NB-1);
    const long base = (long)e * (NJ*128);
    float st[11];

    // precomputed clamped row offsets for MLP phases
    int rowc[8], aoff[8], joff[8], hoff[8];
    #pragma unroll
    for (int i = 0; i < 8; i++) {
        int row = r0+i; rowc[i] = row < NJ ? row : (NJ-1);
        aoff[i] = rowc[i]*132; joff[i] = RO(rowc[i]); hoff[i] = rowc[i]*64;
    }

    float x[8][4];
    #pragma unroll
    for (int i = 0; i < 8; i++) {
        float4 v = *reinterpret_cast<const float4*>(joint + base + rowc[i]*128 + c0);
        x[i][0]=v.x; x[i][1]=v.y; x[i][2]=v.z; x[i][3]=v.w;
    }
    #pragma unroll
    for (int i = 0; i < 8; i++) {
        int row = r0+i;
        float4 v = *reinterpret_cast<const float4*>(rel + base + rowc[i]*128 + c0);
        float mu, inv;
        row_stats4(v.x, v.y, v.z, v.w, mu, inv);
        if (row < NJ) {
            float4 o;
            o.x=(v.x-mu)*inv; o.y=(v.y-mu)*inv; o.z=(v.z-mu)*inv; o.w=(v.w-mu)*inv;
            *reinterpret_cast<float4*>(rn + RO(row) + c0) = o;
        }
    }
    {
        float4 z = make_float4(0.f,0.f,0.f,0.f);
        *reinterpret_cast<float4*>(jn + RO(15) + c0) = z;
        *reinterpret_cast<float4*>(rn + RO(15) + c0) = z;
    }

    #pragma unroll 1
    for (int L = 0; L < NDEPTH; L++) {
        const float* Jw = Jqkv_w + L*49152;
        const float* Iw = Iqk_w  + L*49152;
        const float* Pw = proj_w + L*16384;
        const float* Sw = sI ? Iw : Jw;

        __syncthreads();
        if (tid < 128) {
            int d2 = tid>>4, m = tid&15;
            cbuf[tid] = (m < NJ) ? Iconv_w[L*(8*NJ) + d2*NJ + m] : 0.f;
            ln2c[tid] = ln2_w[L*128 + tid];
        } else if (tid < 144) {
            int m = tid-128;
            cbuf[128+m] = (m < NJ) ? Iconv_b[L*NJ + m] : 0.f;
        }
        if (tid < 384) {
            bfold[tid] = g_bfold[L*384 + tid];
            jbsm[tid]  = Jqkv_b[L*384 + tid];
        }
        {
            float4 w1 = *reinterpret_cast<const float4*>(ln1_w + L*128 + c0);
            float4 b1 = *reinterpret_cast<const float4*>(ln1_b + L*128 + c0);
            #pragma unroll
            for (int i = 0; i < 8; i++) {
                float mu, inv;
                row_stats4(x[i][0], x[i][1], x[i][2], x[i][3], mu, inv);
                int row = r0+i;
                if (row < NJ) {
                    float4 o;
                    o.x = fmaf((x[i][0]-mu)*inv, w1.x, b1.x);
                    o.y = fmaf((x[i][1]-mu)*inv, w1.y, b1.y);
                    o.z = fmaf((x[i][2]-mu)*inv, w1.z, b1.z);
                    o.w = fmaf((x[i][3]-mu)*inv, w1.w, b1.w);
                    *reinterpret_cast<float4*>(jn + RO(row) + c0) = o;
                }
            }
        }
        __syncthreads();

        // prefetch attention chunk (r=0,q=0)
        {
            const float* gp = Sw + gcb0 + kk0*384;
            const float* lp = ln2c + kk0;
            #pragma unroll
            for (int i = 0; i < 8; i++)
                st[i] = sI ? gp[i*1536]*lp[4*i] : gp[i*1536];
        }
        const float* bsrc = sd ? bfold : jbsm;
        #pragma unroll 1
        for (int r = 0; r < 8; r++) {
            const int h = r*2 + ws;
            u64t acc[3][8];
            #pragma unroll
            for (int mt = 0; mt < 3; mt++) {
                float bv = bsrc[mt*128 + h*8 + dd];
                #pragma unroll
                for (int i = 0; i < 8; i++) acc[mt][i] = pk2(bv, 0.f);
            }
            #pragma unroll 1
            for (int q = 0; q < 4; q++) {
                const int p = q & 1;
                #pragma unroll
                for (int i = 0; i < 8; i++) wbuf[ssm0 + p*1728 + 4*i] = st[i];
                asm volatile("bar.sync %0, %1;" :: "r"(2+ws), "r"(192) : "memory");
                {
                    int nr = r, nq = q + 1;
                    if (nq == 4) { nq = 0; nr++; }
                    if (nr < 8) {
                        const float* gp = Sw + gcb0 + nr*16 + (nq*32 + kk0)*384;
                        const float* lp = ln2c + nq*32 + kk0;
                        #pragma unroll
                        for (int i = 0; i < 8; i++)
                            st[i] = sI ? gp[i*1536]*lp[4*i] : gp[i*1536];
                    }
                }
                const float* ap  = jn + sd*RNOFF + rg*1032 + q*32;
                const float* w0p = wbuf + ws*3456 + p*1728 + (sd*24 + dd)*36;
                const float* w1p = w0p + 288;
                const float* w2p = w0p + 576;
                #pragma unroll 4
                for (int k = 0; k < 32; k += 4) {
                    ulonglong2 W0 = *reinterpret_cast<const ulonglong2*>(w0p + k);
                    ulonglong2 W1 = *reinterpret_cast<const ulonglong2*>(w1p + k);
                    ulonglong2 W2 = *reinterpret_cast<const ulonglong2*>(w2p + k);
                    #pragma unroll
                    for (int i = 0; i < 8; i++) {
                        ulonglong2 A = *reinterpret_cast<const ulonglong2*>(ap + i*128 + k);
                        acc[0][i] = fm2(A.x, W0.x, acc[0][i]);
                        acc[0][i] = fm2(A.y, W0.y, acc[0][i]);
                        acc[1][i] = fm2(A.x, W1.x, acc[1][i]);
                        acc[1][i] = fm2(A.y, W1.y, acc[1][i]);
                        acc[2][i] = fm2(A.x, W2.x, acc[2][i]);
                        acc[2][i] = fm2(A.y, W2.y, acc[2][i]);
                    }
                }
            }
            {
                float* qb = qsw + sd*360 + rg*64 + dd;
                #pragma unroll
                for (int mt = 0; mt < 3; mt++) {
                    #pragma unroll
                    for (int i = 0; i < 8; i++) {
                        if (rg*8 + i < NJ) {
                            float lo, hi; up2(acc[mt][i], lo, hi);
                            qb[mt*120 + i*8] = lo + hi;
                        }
                    }
                }
            }
            __syncwarp();
            {
                const int pr = lane >> 4;
                const int n  = lane & 15;
                if (n < NJ) {
                    float sc[NJ];
                    if (pr == 0) {
                        ulonglong2 Q0 = *reinterpret_cast<const ulonglong2*>(qsw + 0*120 + n*8);
                        ulonglong2 Q1 = *reinterpret_cast<const ulonglong2*>(qsw + 0*120 + n*8 + 4);
                        #pragma unroll
                        for (int m = 0; m < NJ; m++) {
                            ulonglong2 K0 = *reinterpret_cast<const ulonglong2*>(qsw + 1*120 + m*8);
                            ulonglong2 K1 = *reinterpret_cast<const ulonglong2*>(qsw + 1*120 + m*8 + 4);
                            u64t t2 = ml2(Q0.x, K0.x);
                            t2 = fm2(Q0.y, K0.y, t2);
                            t2 = fm2(Q1.x, K1.x, t2);
                            t2 = fm2(Q1.y, K1.y, t2);
                            float lo, hi; up2(t2, lo, hi);
                            sc[m] = lo + hi;
                        }
                    } else {
                        ulonglong2 U0 = *reinterpret_cast<const ulonglong2*>(qsw + 3*120 + n*8);
                        ulonglong2 U1 = *reinterpret_cast<const ulonglong2*>(qsw + 3*120 + n*8 + 4);
                        float iv[8];
                        {
                            float4 v0 = *reinterpret_cast<float4*>(qsw + 5*120 + n*8);
                            float4 v1 = *reinterpret_cast<float4*>(qsw + 5*120 + n*8 + 4);
                            iv[0]=v0.x; iv[1]=v0.y; iv[2]=v0.z; iv[3]=v0.w;
                            iv[4]=v1.x; iv[5]=v1.y; iv[6]=v1.z; iv[7]=v1.w;
                        }
                        #pragma unroll
                        for (int m = 0; m < NJ; m++) {
                            ulonglong2 I0 = *reinterpret_cast<const ulonglong2*>(qsw + 4*120 + m*8);
                            ulonglong2 I1 = *reinterpret_cast<const ulonglong2*>(qsw + 4*120 + m*8 + 4);
                            u64t t2 = ml2(U0.x, I0.x);
                            t2 = fm2(U0.y, I0.y, t2);
                            t2 = fm2(U1.x, I1.x, t2);
                            t2 = fm2(U1.y, I1.y, t2);
                            float lo, hi; up2(t2, lo, hi);
                            float t = cbuf[128+m];
                            #pragma unroll
                            for (int d3 = 0; d3 < 8; d3++)
                                t = fmaf(iv[d3], cbuf[d3*16 + m], t);
                            sc[m] = t + lo + hi;
                        }
                    }
                    #pragma unroll
                    for (int m = 0; m < NJ; m++) {
                        float o2 = __shfl_xor_sync(0x7fff7fffu, sc[m], 16);
                        sc[m] = (sc[m] + o2) * 0.6f;
                    }
                    float mx = sc[0];
                    #pragma unroll
                    for (int m = 1; m < NJ; m++) mx = fmaxf(mx, sc[m]);
                    float sum = 0.f;
                    #pragma unroll
                    for (int m = 0; m < NJ; m++) { sc[m] = __expf(sc[m]-mx); sum += sc[m]; }
                    float rs = 1.0f/sum;
                    u64t o0 = 0ull, o1 = 0ull;
                    const float* jvh = qsw + 2*120 + pr*4;
                    #pragma unroll
                    for (int m = 0; m < NJ; m++) {
                        float pm = sc[m]*rs;
                        u64t pm2 = pk2(pm, pm);
                        ulonglong2 Jh = *reinterpret_cast<const ulonglong2*>(jvh + m*8);
                        o0 = fm2(pm2, Jh.x, o0);
                        o1 = fm2(pm2, Jh.y, o1);
                    }
                    *reinterpret_cast<ulonglong2*>(ao + n*132 + h*8 + pr*4) =
                        make_ulonglong2(o0, o1);
                }
            }
        }

        // ---- proj: ping-pong staging ----
        #pragma unroll
        for (int i = 0; i < 11; i++) {
            int idx = tid + i*384;
            if (idx < 4096) st[i] = Pw[idx];
        }
        __syncthreads();
        u64t xa[8], xb[8];
        #pragma unroll
        for (int i = 0; i < 8; i++) { xa[i]=pk2(x[i][0],x[i][1]); xb[i]=pk2(x[i][2],x[i][3]); }
        #pragma unroll 1
        for (int kc = 0; kc < 4; kc++) {
            float* bp = wbuf + (kc&1)*4096;
            #pragma unroll
            for (int i = 0; i < 11; i++) {
                int idx = tid + i*384;
                if (idx < 4096) bp[idx] = st[i];
            }
            __syncthreads();
            if (kc < 3) {
                #pragma unroll
                for (int i = 0; i < 11; i++) {
                    int idx = tid + i*384;
                    if (idx < 4096) st[i] = Pw[(kc+1)*4096 + idx];
                }
            }
            #pragma unroll 2
            for (int kk4 = 0; kk4 < 8; kk4++) {
                float a4[8][4];
                #pragma unroll
                for (int i = 0; i < 8; i++) {
                    float4 t = *reinterpret_cast<float4*>(ao + aoff[i] + kc*32 + kk4*4);
                    a4[i][0]=t.x; a4[i][1]=t.y; a4[i][2]=t.z; a4[i][3]=t.w;
                }
                #pragma unroll
                for (int j = 0; j < 4; j++) {
                    ulonglong2 Wv = *reinterpret_cast<const ulonglong2*>(bp + (kk4*4+j)*128 + c0);
                    #pragma unroll
                    for (int i = 0; i < 8; i++) {
                        u64t ad = pk2(a4[i][j], a4[i][j]);
                        xa[i] = fm2(ad, Wv.x, xa[i]);
                        xb[i] = fm2(ad, Wv.y, xb[i]);
                    }
                }
            }
        }
        #pragma unroll
        for (int i = 0; i < 8; i++) { up2(xa[i],x[i][0],x[i][1]); up2(xb[i],x[i][2],x[i][3]); }
        {
            float4 pb = *reinterpret_cast<const float4*>(proj_b + L*128 + c0);
            #pragma unroll
            for (int i = 0; i < 8; i++) {
                x[i][0]+=pb.x; x[i][1]+=pb.y; x[i][2]+=pb.z; x[i][3]+=pb.w;
            }
        }
        {
            float4 w3 = *reinterpret_cast<const float4*>(ln3_w + L*128 + c0);
            float4 b3 = *reinterpret_cast<const float4*>(ln3_b + L*128 + c0);
            #pragma unroll
            for (int i = 0; i < 8; i++) {
                float mu, inv;
                row_stats4(x[i][0], x[i][1], x[i][2], x[i][3], mu, inv);
                int row = r0+i;
                if (row < NJ) {
                    float4 o;
                    o.x = fmaf((x[i][0]-mu)*inv, w3.x, b3.x);
                    o.y = fmaf((x[i][1]-mu)*inv, w3.y, b3.y);
                    o.z = fmaf((x[i][2]-mu)*inv, w3.z, b3.z);
                    o.w = fmaf((x[i][3]-mu)*inv, w3.w, b3.w);
                    *reinterpret_cast<float4*>(jn + RO(row) + c0) = o;
                }
            }
        }
        // ---- fc1 ----
        u64t ha2[8];
        {
            float2 fb = *reinterpret_cast<const float2*>(fc1_b + L*64 + lane*2);
            #pragma unroll
            for (int i = 0; i < 8; i++) ha2[i] = pk2(fb.x, fb.y);
        }
        #pragma unroll
        for (int i = 0; i < 11; i++) {
            int idx = tid + i*384;
            if (idx < 4096) st[i] = fc1_w[L*8192 + idx];
        }
        #pragma unroll 1
        for (int kc = 0; kc < 2; kc++) {
            float* bp = wbuf + (kc&1)*4096;
            #pragma unroll
            for (int i = 0; i < 11; i++) {
                int idx = tid + i*384;
                if (idx < 4096) bp[idx] = st[i];
            }
            __syncthreads();
            if (kc < 1) {
                #pragma unroll
                for (int i = 0; i < 11; i++) {
                    int idx = tid + i*384;
                    if (idx < 4096) st[i] = fc1_w[L*8192 + 4096 + idx];
                }
            }
            #pragma unroll 2
            for (int kk4 = 0; kk4 < 16; kk4++) {
                float a4[8][4];
                #pragma unroll
                for (int i = 0; i < 8; i++) {
                    float4 t = *reinterpret_cast<float4*>(jn + joff[i] + kc*64 + kk4*4);
                    a4[i][0]=t.x; a4[i][1]=t.y; a4[i][2]=t.z; a4[i][3]=t.w;
                }
                #pragma unroll
                for (int j = 0; j < 4; j++) {
                    u64t wv = *reinterpret_cast<const u64t*>(bp + (kk4*4+j)*64 + lane*2);
                    #pragma unroll
                    for (int i = 0; i < 8; i++) {
                        u64t ad = pk2(a4[i][j], a4[i][j]);
                        ha2[i] = fm2(ad, wv, ha2[i]);
                    }
                }
            }
        }
        #pragma unroll
        for (int i = 0; i < 8; i++) {
            int row = r0+i;
            if (row < NJ) {
                float h0, h1; up2(ha2[i], h0, h1);
                float g0 = 0.5f*h0*(1.0f + erff(h0*0.70710678118654752f));
                float g1 = 0.5f*h1*(1.0f + erff(h1*0.70710678118654752f));
                *reinterpret_cast<float2*>(ao + row*64 + lane*2) = make_float2(g0, g1);
            }
        }
        __syncwarp();
        // ---- fc2 ----
        #pragma unroll
        for (int i = 0; i < 11; i++) {
            int idx = tid + i*384;
            if (idx < 4096) st[i] = fc2_w[L*8192 + idx];
        }
        #pragma unroll
        for (int i = 0; i < 8; i++) { xa[i]=pk2(x[i][0],x[i][1]); xb[i]=pk2(x[i][2],x[i][3]); }
        #pragma unroll 1
        for (int kc = 0; kc < 2; kc++) {
            float* bp = wbuf + (kc&1)*4096;
            #pragma unroll
            for (int i = 0; i < 11; i++) {
                int idx = tid + i*384;
                if (idx < 4096) bp[idx] = st[i];
            }
            __syncthreads();
            if (kc < 1) {
                #pragma unroll
                for (int i = 0; i < 11; i++) {
                    int idx = tid + i*384;
                    if (idx < 4096) st[i] = fc2_w[L*8192 + 4096 + idx];
                }
            }
            #pragma unroll 2
            for (int kk4 = 0; kk4 < 8; kk4++) {
                float a4[8][4];
                #pragma unroll
                for (int i = 0; i < 8; i++) {
                    float4 t = *reinterpret_cast<float4*>(ao + hoff[i] + kc*32 + kk4*4);
                    a4[i][0]=t.x; a4[i][1]=t.y; a4[i][2]=t.z; a4[i][3]=t.w;
                }
                #pragma unroll
                for (int j = 0; j < 4; j++) {
                    ulonglong2 Wv = *reinterpret_cast<const ulonglong2*>(bp + (kk4*4+j)*128 + c0);
                    #pragma unroll
                    for (int i = 0; i < 8; i++) {
                        u64t ad = pk2(a4[i][j], a4[i][j]);
                        xa[i] = fm2(ad, Wv.x, xa[i]);
                        xb[i] = fm2(ad, Wv.y, xb[i]);
                    }
                }
            }
        }
        #pragma unroll
        for (int i = 0; i < 8; i++) { up2(xa[i],x[i][0],x[i][1]); up2(xb[i],x[i][2],x[i][3]); }
        {
            float4 fb = *reinterpret_cast<const float4*>(fc2_b + L*128 + c0);
            #pragma unroll
            for (int i = 0; i < 8; i++) {
                x[i][0]+=fb.x; x[i][1]+=fb.y; x[i][2]+=fb.z; x[i][3]+=fb.w;
            }
        }
    }

    if (eb < NB) {
        #pragma unroll
        for (int i = 0; i < 8; i++) {
            int row = r0+i;
            if (row < NJ)
                *reinterpret_cast<float4*>(out + base + row*128 + c0) =
                    make_float4(x[i][0], x[i][1], x[i][2], x[i][3]);
        }
    }
}

extern "C" void kernel_launch(void* const* d_in, const int* in_sizes, int n_in,
                              void* d_out, int out_size) {
    (void)in_sizes; (void)n_in; (void)out_size;
    const float** p = (const float**)d_in;
    bfold_prep<<<NDEPTH, 384>>>(p[5], p[4], p[13]);
    cudaFuncSetAttribute(jr_kernel, cudaFuncAttributeMaxDynamicSharedMemorySize,
                         SMEM_BYTES);
    jr_kernel<<<(NB + EPC - 1)/EPC, NTHR, SMEM_BYTES>>>(
        p[0], p[1], p[2], p[3], p[4], p[5], p[6], p[7], p[8], p[9],
        p[10], p[11], p[12], p[13], p[14], p[15], p[16], p[17], p[18], p[19],
        (float*)d_out);
}